// round 12
// baseline (speedup 1.0000x reference)
#include <cuda_runtime.h>
#include <cuda_fp16.h>
#include <math.h>
#include <stdint.h>

#define Bb 2
#define Tt 4096
#define Cc 768
#define NHh 12
#define HSs 64
#define BT (Bb*Tt)
#define C3 (3*Cc)

__device__ __half g_qkv[(size_t)BT * C3];   // [B*T, 3C] fp16
__device__ __half g_att[(size_t)BT * Cc];   // [B*T, C]  fp16
__device__ __half g_xh [(size_t)BT * Cc];   // x in fp16
__device__ __half g_wa [(size_t)Cc * C3];   // w_attn fp16
__device__ __half g_wp [(size_t)Cc * Cc];   // w_proj fp16

__device__ __forceinline__ uint32_t h2u(__half2 h) {
    return *reinterpret_cast<uint32_t*>(&h);
}
__device__ __forceinline__ uint32_t pk(float a, float b) {
    __half2 h = __floats2half2_rn(a, b);
    return h2u(h);
}
__device__ __forceinline__ float ex2(float x) {
    float r;
    asm("ex2.approx.ftz.f32 %0, %1;" : "=f"(r) : "f"(x));
    return r;
}
__device__ __forceinline__ uint32_t ex2h2(uint32_t x) {
    uint32_t r;
    asm("ex2.approx.f16x2 %0, %1;" : "=r"(r) : "r"(x));
    return r;
}
__device__ __forceinline__ void cp16(uint32_t dst, const void* src) {
    asm volatile("cp.async.cg.shared.global [%0], [%1], 16;" :: "r"(dst), "l"(src));
}
__device__ __forceinline__ void cp_commit() { asm volatile("cp.async.commit_group;"); }
__device__ __forceinline__ void cp_wait1()  { asm volatile("cp.async.wait_group 1;"); }
__device__ __forceinline__ void cp_wait0()  { asm volatile("cp.async.wait_group 0;"); }

__device__ __forceinline__ void mma_f16(float c[4], const uint32_t a[4], const uint32_t b[2]) {
    asm volatile(
        "mma.sync.aligned.m16n8k16.row.col.f32.f16.f16.f32 "
        "{%0,%1,%2,%3},{%4,%5,%6,%7},{%8,%9},{%0,%1,%2,%3};"
        : "+f"(c[0]), "+f"(c[1]), "+f"(c[2]), "+f"(c[3])
        : "r"(a[0]), "r"(a[1]), "r"(a[2]), "r"(a[3]), "r"(b[0]), "r"(b[1]));
}
__device__ __forceinline__ void ldsm4(uint32_t r[4], uint32_t saddr) {
    asm volatile("ldmatrix.sync.aligned.m8n8.x4.shared.b16 {%0,%1,%2,%3}, [%4];"
                 : "=r"(r[0]), "=r"(r[1]), "=r"(r[2]), "=r"(r[3]) : "r"(saddr));
}
__device__ __forceinline__ void ldsm4t(uint32_t r[4], uint32_t saddr) {
    asm volatile("ldmatrix.sync.aligned.m8n8.x4.trans.shared.b16 {%0,%1,%2,%3}, [%4];"
                 : "=r"(r[0]), "=r"(r[1]), "=r"(r[2]), "=r"(r[3]) : "r"(saddr));
}
__device__ __forceinline__ uint32_t cvs(const void* p) {
    return (uint32_t)__cvta_generic_to_shared(p);
}

// ---------------------------------------------------------------------------
// fp32 -> fp16 bulk convert, all three tensors in one launch
// ---------------------------------------------------------------------------
__global__ void f2h3(const float* __restrict__ s0, __half* __restrict__ d0, int n0,
                     const float* __restrict__ s1, __half* __restrict__ d1, int n1,
                     const float* __restrict__ s2, __half* __restrict__ d2, int n2)
{
    int i = blockIdx.x * blockDim.x + threadIdx.x;
    const float* s; __half* d; int j;
    if (i < n0)           { s = s0; d = d0; j = i; }
    else if (i < n0 + n1) { s = s1; d = d1; j = i - n0; }
    else if (i < n0 + n1 + n2) { s = s2; d = d2; j = i - n0 - n1; }
    else return;
    float4 v = *(const float4*)(s + (size_t)j * 4);
    uint2 u;
    u.x = pk(v.x, v.y);
    u.y = pk(v.z, v.w);
    *(uint2*)(d + (size_t)j * 4) = u;
}

// ---------------------------------------------------------------------------
// All-half GEMM: CTA 128x256, 8 warps, warp 64x64, kc=32.
// 3-stage cp.async ring, ONE __syncthreads per k-chunk.
// ---------------------------------------------------------------------------
#define LDAH 40
#define LDBH 264
#define GSTG (128 * LDAH + 32 * LDBH)       // halfs per stage (13568)
#define GA_H(s) ((s) * GSTG)
#define GB_H(s) ((s) * GSTG + 128 * LDAH)
#define GEMM_SMEM_H (3 * GSTG)              // 40704 halfs = 81408 B

template <typename TC>
__global__ __launch_bounds__(256)
void gemm_h16(const __half* __restrict__ A, const __half* __restrict__ B,
              TC* __restrict__ C, int M, int N, int K)
{
    extern __shared__ __half smh[];

    const int tid = threadIdx.x;
    const int lane = tid & 31, wid = tid >> 5;
    const int warpM = wid >> 2, warpN = wid & 3;
    const int lr = lane >> 2, lc = lane & 3;
    const int brow = blockIdx.y << 7, bcol = blockIdx.x << 8;

    const __half* Ab = A + (size_t)brow * K;
    const __half* Bbp = B + bcol;

    float acc[4][8][4];
    #pragma unroll
    for (int i = 0; i < 4; i++)
        #pragma unroll
        for (int j = 0; j < 8; j++)
            #pragma unroll
            for (int q = 0; q < 4; q++) acc[i][j][q] = 0.f;

    #define ISSUE(kt, s) do { \
        uint32_t as_ = cvs(smh + GA_H(s)); \
        uint32_t bs_ = cvs(smh + GB_H(s)); \
        _Pragma("unroll") \
        for (int it = 0; it < 2; it++) { \
            int idx = tid + it * 256; \
            int r = idx >> 2, c8 = (idx & 3) << 3; \
            cp16(as_ + (uint32_t)(r * LDAH + c8) * 2u, \
                 Ab + (size_t)r * K + (kt) * 32 + c8); \
        } \
        _Pragma("unroll") \
        for (int it = 0; it < 4; it++) { \
            int idx = tid + it * 256; \
            int r = idx >> 5, c8 = (idx & 31) << 3; \
            cp16(bs_ + (uint32_t)(r * LDBH + c8) * 2u, \
                 Bbp + (size_t)((kt) * 32 + r) * N + c8); \
        } \
        cp_commit(); \
    } while (0)

    const int NT = K >> 5;
    ISSUE(0, 0);
    ISSUE(1 < NT ? 1 : NT - 1, 1);

    const int aRow = lane & 15, aKoff = (lane & 16) ? 8 : 0;
    const int bRow = (lane & 7) + ((lane & 8) ? 8 : 0);
    const int bNoff = (lane & 16) ? 8 : 0;

    for (int kt = 0; kt < NT; kt++) {
        const int cur = kt % 3;
        cp_wait1();            // stage kt ready (2 groups in flight max)
        __syncthreads();       // also proves stage kt-1 reads done
        {
            int nk = kt + 2 < NT ? kt + 2 : NT - 1;
            ISSUE(nk, (kt + 2) % 3);
        }

        const __half* Ac = smh + GA_H(cur);
        const __half* Bc = smh + GB_H(cur);
        #pragma unroll
        for (int ks = 0; ks < 2; ks++) {
            uint32_t af[4][4];
            #pragma unroll
            for (int mt = 0; mt < 4; mt++)
                ldsm4(af[mt], cvs(Ac + (warpM * 64 + mt * 16 + aRow) * LDAH
                                     + ks * 16 + aKoff));
            uint32_t bf[8][2];
            #pragma unroll
            for (int j2 = 0; j2 < 4; j2++) {
                uint32_t t[4];
                ldsm4t(t, cvs(Bc + (ks * 16 + bRow) * LDBH
                                 + warpN * 64 + j2 * 16 + bNoff));
                bf[2 * j2][0] = t[0]; bf[2 * j2][1] = t[1];
                bf[2 * j2 + 1][0] = t[2]; bf[2 * j2 + 1][1] = t[3];
            }
            #pragma unroll
            for (int mt = 0; mt < 4; mt++)
                #pragma unroll
                for (int nt = 0; nt < 8; nt++)
                    mma_f16(acc[mt][nt], af[mt], bf[nt]);
        }
    }

    #pragma unroll
    for (int mt = 0; mt < 4; mt++)
        #pragma unroll
        for (int nt = 0; nt < 8; nt++) {
            int row = brow + warpM * 64 + mt * 16 + lr;
            int col = bcol + warpN * 64 + nt * 8 + 2 * lc;
            if constexpr (sizeof(TC) == 2) {
                *(__half2*)&C[(size_t)row * N + col] =
                    __floats2half2_rn(acc[mt][nt][0], acc[mt][nt][1]);
                *(__half2*)&C[(size_t)(row + 8) * N + col] =
                    __floats2half2_rn(acc[mt][nt][2], acc[mt][nt][3]);
            } else {
                *(float2*)&C[(size_t)row * N + col] =
                    make_float2(acc[mt][nt][0], acc[mt][nt][1]);
                *(float2*)&C[(size_t)(row + 8) * N + col] =
                    make_float2(acc[mt][nt][2], acc[mt][nt][3]);
            }
        }
    #undef ISSUE
}

// ---------------------------------------------------------------------------
// Causal flash attention: fp16 mma, register softmax (base-2), f16x2 exp,
// l via ones-mma. 128-key stages, 3-stage cp.async ring, ONE sync per stage.
// 1-D grid in LPT (heaviest-first) order.
// ---------------------------------------------------------------------------
#define LDFH 72
#define KBUF (128 * LDFH)       // one 128x64 tile (halfs)
#define FSTG (2 * KBUF)         // K+V per stage
#define FLASH_SMEM_H (3 * FSTG) // 55296 halfs = 110592 B

__global__ __launch_bounds__(256)
void flash_f16(const __half* __restrict__ qkv, __half* __restrict__ out)
{
    extern __shared__ __half smf[];
    __half* Qstage = smf;

    // LPT order: first 24 blocks are qt=15 (all heads/batches), then qt=14, ...
    const int NQT = Tt / 256;                 // 16
    const int qt = NQT - 1 - ((int)blockIdx.x / (NHh * Bb));
    const int hb = (int)blockIdx.x % (NHh * Bb);
    const int h = hb % NHh, b = hb / NHh;

    const int tid = threadIdx.x;
    const int lane = tid & 31, w = tid >> 5;
    const int lr = lane >> 2, lc = lane & 3;
    const float NEG = -1e30f;
    const float qscale = 0.125f * 1.44269504089f;

    const int q0 = qt * 256;
    const size_t qrow0 = (size_t)(b * Tt + q0);
    const __half* qbase = qkv + qrow0 * C3 + h * HSs;

    {
        const __half* qr = qbase + (size_t)tid * C3;
        __half* qd = Qstage + tid * LDFH;
        #pragma unroll
        for (int c8 = 0; c8 < 64; c8 += 8) {
            uint4 u = *(const uint4*)(qr + c8);
            __half2* hp = (__half2*)&u;
            #pragma unroll
            for (int q = 0; q < 4; q++) {
                float2 f = __half22float2(hp[q]);
                hp[q] = __floats2half2_rn(f.x * qscale, f.y * qscale);
            }
            *(uint4*)(qd + c8) = u;
        }
    }
    __syncthreads();

    const int aRow = lane & 15, aKoff = (lane & 16) ? 8 : 0;
    uint32_t qf[2][4][4];
    #pragma unroll
    for (int mt = 0; mt < 2; mt++)
        #pragma unroll
        for (int ks = 0; ks < 4; ks++)
            ldsm4(qf[mt][ks], cvs(Qstage + (w * 32 + mt * 16 + aRow) * LDFH
                                     + ks * 16 + aKoff));
    __syncthreads();   // qf extracted before stage buffers overwritten

    const int nIter = 2 * qt + 2;            // 128-key tiles
    const __half* kvb = qkv + (size_t)(b * Tt) * C3 + Cc + h * HSs;

    #define ISSUEF(jb_, s_) do { \
        const __half* kb_ = kvb + (size_t)(jb_) * 128 * C3; \
        uint32_t kd_ = cvs(smf + (s_) * FSTG); \
        uint32_t vd_ = kd_ + KBUF * 2; \
        _Pragma("unroll") \
        for (int it = 0; it < 4; it++) { \
            int idx = tid + it * 256; \
            int r = idx >> 3, c8 = (idx & 7) << 3; \
            size_t go = (size_t)r * C3 + c8; \
            uint32_t so = (uint32_t)(r * LDFH + c8) * 2u; \
            cp16(kd_ + so, kb_ + go); \
            cp16(vd_ + so, kb_ + Cc + go); \
        } \
        cp_commit(); \
    } while (0)

    ISSUEF(0, 0);
    ISSUEF(1 < nIter ? 1 : nIter - 1, 1);

    float accO[2][8][4];
    float lAcc[2][4];
    #pragma unroll
    for (int mt = 0; mt < 2; mt++) {
        #pragma unroll
        for (int j = 0; j < 8; j++)
            #pragma unroll
            for (int q = 0; q < 4; q++) accO[mt][j][q] = 0.f;
        #pragma unroll
        for (int q = 0; q < 4; q++) lAcc[mt][q] = 0.f;
    }
    float mrun[2][2] = {{NEG, NEG}, {NEG, NEG}};
    const uint32_t ONES2 = 0x3C003C00u;
    const uint32_t onesB[2] = {ONES2, ONES2};

    const int kRow = (lane & 7) + ((lane & 8) ? 8 : 0);
    const int kOff = (lane & 16) ? 8 : 0;

    for (int jb = 0; jb < nIter; jb++) {
        const int cur = jb % 3;
        __half* Kt = smf + cur * FSTG;
        __half* Vt = Kt + KBUF;

        cp_wait1();            // stage jb arrived
        __syncthreads();       // stage jb-1 reads complete
        {
            int nk = jb + 2 < nIter ? jb + 2 : nIter - 1;
            ISSUEF(nk, (jb + 2) % 3);
        }

        #pragma unroll
        for (int sub = 0; sub < 2; sub++) {
            const int kb64 = jb * 2 + sub;
            __half* Ks = Kt + sub * 64 * LDFH;
            __half* Vs = Vt + sub * 64 * LDFH;

            // ---- S = Q x K^T ----
            float sAcc[2][8][4];
            #pragma unroll
            for (int mt = 0; mt < 2; mt++)
                #pragma unroll
                for (int j = 0; j < 8; j++)
                    #pragma unroll
                    for (int q = 0; q < 4; q++) sAcc[mt][j][q] = 0.f;

            #pragma unroll
            for (int ks = 0; ks < 4; ks++) {
                uint32_t kf[8][2];
                #pragma unroll
                for (int j2 = 0; j2 < 4; j2++) {
                    uint32_t t[4];
                    ldsm4(t, cvs(Ks + (j2 * 16 + kRow) * LDFH + ks * 16 + kOff));
                    kf[2 * j2][0] = t[0]; kf[2 * j2][1] = t[2];
                    kf[2 * j2 + 1][0] = t[1]; kf[2 * j2 + 1][1] = t[3];
                }
                #pragma unroll
                for (int nj = 0; nj < 8; nj++) {
                    mma_f16(sAcc[0][nj], qf[0][ks], kf[nj]);
                    mma_f16(sAcc[1][nj], qf[1][ks], kf[nj]);
                }
            }

            // ---- mask + online softmax ----
            uint32_t paf[2][4][4];
            #pragma unroll
            for (int mt = 0; mt < 2; mt++) {
                const int rowA = q0 + w * 32 + mt * 16 + lr;
                const int rowB = rowA + 8;
                if (kb64 * 64 + 63 > q0 + w * 32 + mt * 16) {
                    #pragma unroll
                    for (int nj = 0; nj < 8; nj++) {
                        int col = kb64 * 64 + nj * 8 + 2 * lc;
                        if (col > rowA)     sAcc[mt][nj][0] = NEG;
                        if (col + 1 > rowA) sAcc[mt][nj][1] = NEG;
                        if (col > rowB)     sAcc[mt][nj][2] = NEG;
                        if (col + 1 > rowB) sAcc[mt][nj][3] = NEG;
                    }
                }

                float mxA = NEG, mxB = NEG;
                #pragma unroll
                for (int nj = 0; nj < 8; nj++) {
                    mxA = fmaxf(mxA, fmaxf(sAcc[mt][nj][0], sAcc[mt][nj][1]));
                    mxB = fmaxf(mxB, fmaxf(sAcc[mt][nj][2], sAcc[mt][nj][3]));
                }
                mxA = fmaxf(mxA, __shfl_xor_sync(0xffffffffu, mxA, 1));
                mxA = fmaxf(mxA, __shfl_xor_sync(0xffffffffu, mxA, 2));
                mxB = fmaxf(mxB, __shfl_xor_sync(0xffffffffu, mxB, 1));
                mxB = fmaxf(mxB, __shfl_xor_sync(0xffffffffu, mxB, 2));

                float mn0 = fmaxf(mrun[mt][0], mxA), mn1 = fmaxf(mrun[mt][1], mxB);
                float al0 = ex2(mrun[mt][0] - mn0), al1 = ex2(mrun[mt][1] - mn1);
                mrun[mt][0] = mn0; mrun[mt][1] = mn1;

                #pragma unroll
                for (int ks = 0; ks < 4; ks++) {
                    paf[mt][ks][0] = ex2h2(pk(sAcc[mt][2 * ks][0] - mn0,
                                              sAcc[mt][2 * ks][1] - mn0));
                    paf[mt][ks][1] = ex2h2(pk(sAcc[mt][2 * ks][2] - mn1,
                                              sAcc[mt][2 * ks][3] - mn1));
                    paf[mt][ks][2] = ex2h2(pk(sAcc[mt][2 * ks + 1][0] - mn0,
                                              sAcc[mt][2 * ks + 1][1] - mn0));
                    paf[mt][ks][3] = ex2h2(pk(sAcc[mt][2 * ks + 1][2] - mn1,
                                              sAcc[mt][2 * ks + 1][3] - mn1));
                }

                #pragma unroll
                for (int nj = 0; nj < 8; nj++) {
                    accO[mt][nj][0] *= al0; accO[mt][nj][1] *= al0;
                    accO[mt][nj][2] *= al1; accO[mt][nj][3] *= al1;
                }
                lAcc[mt][0] *= al0; lAcc[mt][1] *= al0;
                lAcc[mt][2] *= al1; lAcc[mt][3] *= al1;

                #pragma unroll
                for (int ks = 0; ks < 4; ks++)
                    mma_f16(lAcc[mt], paf[mt][ks], onesB);
            }

            // ---- O += P x V ----
            #pragma unroll
            for (int ks = 0; ks < 4; ks++) {
                uint32_t vf[8][2];
                #pragma unroll
                for (int j2 = 0; j2 < 4; j2++) {
                    uint32_t t[4];
                    ldsm4t(t, cvs(Vs + (ks * 16 + kRow) * LDFH + j2 * 16 + kOff));
                    vf[2 * j2][0] = t[0]; vf[2 * j2][1] = t[1];
                    vf[2 * j2 + 1][0] = t[2]; vf[2 * j2 + 1][1] = t[3];
                }
                #pragma unroll
                for (int nj = 0; nj < 8; nj++) {
                    mma_f16(accO[0][nj], paf[0][ks], vf[nj]);
                    mma_f16(accO[1][nj], paf[1][ks], vf[nj]);
                }
            }
        }
    }

    cp_wait0();

    __half* obase = out + qrow0 * Cc + h * HSs;
    #pragma unroll
    for (int mt = 0; mt < 2; mt++) {
        int r0 = w * 32 + mt * 16 + lr;
        float rl0 = 1.f / lAcc[mt][0], rl1 = 1.f / lAcc[mt][2];
        #pragma unroll
        for (int nj = 0; nj < 8; nj++) {
            int col = nj * 8 + 2 * lc;
            *(__half2*)(obase + (size_t)r0 * Cc + col) =
                __floats2half2_rn(accO[mt][nj][0] * rl0, accO[mt][nj][1] * rl0);
            *(__half2*)(obase + (size_t)(r0 + 8) * Cc + col) =
                __floats2half2_rn(accO[mt][nj][2] * rl1, accO[mt][nj][3] * rl1);
        }
    }
    #undef ISSUEF
}

// ---------------------------------------------------------------------------
extern "C" void kernel_launch(void* const* d_in, const int* in_sizes, int n_in,
                              void* d_out, int out_size)
{
    const float* x      = (const float*)d_in[0];
    const float* w_attn = (const float*)d_in[1];
    const float* w_proj = (const float*)d_in[2];
    float* out = (float*)d_out;

    __half *qkv, *att, *xh, *wa, *wp;
    cudaGetSymbolAddress((void**)&qkv, g_qkv);
    cudaGetSymbolAddress((void**)&att, g_att);
    cudaGetSymbolAddress((void**)&xh, g_xh);
    cudaGetSymbolAddress((void**)&wa, g_wa);
    cudaGetSymbolAddress((void**)&wp, g_wp);

    const int GEMM_SMEM = GEMM_SMEM_H * sizeof(__half);     // 81408 B
    const int FLASH_SMEM = FLASH_SMEM_H * sizeof(__half);   // 110592 B
    cudaFuncSetAttribute(gemm_h16<__half>,
                         cudaFuncAttributeMaxDynamicSharedMemorySize, GEMM_SMEM);
    cudaFuncSetAttribute(gemm_h16<float>,
                         cudaFuncAttributeMaxDynamicSharedMemorySize, GEMM_SMEM);
    cudaFuncSetAttribute(flash_f16,
                         cudaFuncAttributeMaxDynamicSharedMemorySize, FLASH_SMEM);

    // 0) fp32 -> fp16 conversions (single launch)
    {
        int n0 = BT * Cc / 4, n1 = Cc * C3 / 4, n2 = Cc * Cc / 4;
        int nt = n0 + n1 + n2;
        f2h3<<<(nt + 255) / 256, 256>>>(x, xh, n0, w_attn, wa, n1, w_proj, wp, n2);
    }
    // 1) QKV projection (all-half, 128x256 tiles, 3-stage ring)
    gemm_h16<__half><<<dim3(C3 / 256, BT / 128), 256, GEMM_SMEM>>>(
        xh, wa, qkv, BT, C3, Cc);
    // 2) Causal flash attention (128-key 3-stage ring, LPT order)
    flash_f16<<<(Tt / 256) * NHh * Bb, 256, FLASH_SMEM>>>(qkv, att);
    // 3) Output projection (half in, float out)
    gemm_h16<float><<<dim3(Cc / 256, BT / 128), 256, GEMM_SMEM>>>(
        att, wp, out, BT, Cc, Cc);
}

// round 14
// speedup vs baseline: 1.4733x; 1.4733x over previous
#include <cuda_runtime.h>
#include <cuda_fp16.h>
#include <math.h>
#include <stdint.h>

#define Bb 2
#define Tt 4096
#define Cc 768
#define NHh 12
#define HSs 64
#define BT (Bb*Tt)
#define C3 (3*Cc)

__device__ __half g_qkv[(size_t)BT * C3];   // [B*T, 3C] fp16
__device__ __half g_att[(size_t)BT * Cc];   // [B*T, C]  fp16
__device__ __half g_xh [(size_t)BT * Cc];   // x in fp16
__device__ __half g_wa [(size_t)Cc * C3];   // w_attn fp16
__device__ __half g_wp [(size_t)Cc * Cc];   // w_proj fp16

__device__ __forceinline__ uint32_t h2u(__half2 h) {
    return *reinterpret_cast<uint32_t*>(&h);
}
__device__ __forceinline__ uint32_t pk(float a, float b) {
    __half2 h = __floats2half2_rn(a, b);
    return h2u(h);
}
__device__ __forceinline__ float ex2(float x) {
    float r;
    asm("ex2.approx.ftz.f32 %0, %1;" : "=f"(r) : "f"(x));
    return r;
}
__device__ __forceinline__ uint32_t ex2h2(uint32_t x) {
    uint32_t r;
    asm("ex2.approx.f16x2 %0, %1;" : "=r"(r) : "r"(x));
    return r;
}
__device__ __forceinline__ void cp16(uint32_t dst, const void* src) {
    asm volatile("cp.async.cg.shared.global [%0], [%1], 16;" :: "r"(dst), "l"(src));
}
__device__ __forceinline__ void cp_commit() { asm volatile("cp.async.commit_group;"); }
__device__ __forceinline__ void cp_wait1()  { asm volatile("cp.async.wait_group 1;"); }
__device__ __forceinline__ void cp_wait0()  { asm volatile("cp.async.wait_group 0;"); }

__device__ __forceinline__ void mma_f16(float c[4], const uint32_t a[4], const uint32_t b[2]) {
    asm volatile(
        "mma.sync.aligned.m16n8k16.row.col.f32.f16.f16.f32 "
        "{%0,%1,%2,%3},{%4,%5,%6,%7},{%8,%9},{%0,%1,%2,%3};"
        : "+f"(c[0]), "+f"(c[1]), "+f"(c[2]), "+f"(c[3])
        : "r"(a[0]), "r"(a[1]), "r"(a[2]), "r"(a[3]), "r"(b[0]), "r"(b[1]));
}
__device__ __forceinline__ void ldsm4(uint32_t r[4], uint32_t saddr) {
    asm volatile("ldmatrix.sync.aligned.m8n8.x4.shared.b16 {%0,%1,%2,%3}, [%4];"
                 : "=r"(r[0]), "=r"(r[1]), "=r"(r[2]), "=r"(r[3]) : "r"(saddr));
}
__device__ __forceinline__ void ldsm4t(uint32_t r[4], uint32_t saddr) {
    asm volatile("ldmatrix.sync.aligned.m8n8.x4.trans.shared.b16 {%0,%1,%2,%3}, [%4];"
                 : "=r"(r[0]), "=r"(r[1]), "=r"(r[2]), "=r"(r[3]) : "r"(saddr));
}
__device__ __forceinline__ uint32_t cvs(const void* p) {
    return (uint32_t)__cvta_generic_to_shared(p);
}

// ---------------------------------------------------------------------------
// fp32 -> fp16 bulk convert, all three tensors in one launch
// ---------------------------------------------------------------------------
__global__ void f2h3(const float* __restrict__ s0, __half* __restrict__ d0, int n0,
                     const float* __restrict__ s1, __half* __restrict__ d1, int n1,
                     const float* __restrict__ s2, __half* __restrict__ d2, int n2)
{
    int i = blockIdx.x * blockDim.x + threadIdx.x;
    const float* s; __half* d; int j;
    if (i < n0)           { s = s0; d = d0; j = i; }
    else if (i < n0 + n1) { s = s1; d = d1; j = i - n0; }
    else if (i < n0 + n1 + n2) { s = s2; d = d2; j = i - n0 - n1; }
    else return;
    float4 v = *(const float4*)(s + (size_t)j * 4);
    uint2 u;
    u.x = pk(v.x, v.y);
    u.y = pk(v.z, v.w);
    *(uint2*)(d + (size_t)j * 4) = u;
}

// ---------------------------------------------------------------------------
// All-half GEMM (R11/R9 proven config): CTA 128x256, 8 warps, warp 64x64,
// kc=32, double-buffered cp.async, 2 syncs per chunk.
// ---------------------------------------------------------------------------
#define LDAH 40
#define LDBH 264
#define GA_H(s) ((s) * 128 * LDAH)
#define GB_H(s) (2 * 128 * LDAH + (s) * 32 * LDBH)
#define GEMM_SMEM_H (2 * 128 * LDAH + 2 * 32 * LDBH)

template <typename TC>
__global__ __launch_bounds__(256)
void gemm_h16(const __half* __restrict__ A, const __half* __restrict__ B,
              TC* __restrict__ C, int M, int N, int K)
{
    extern __shared__ __half smh[];

    const int tid = threadIdx.x;
    const int lane = tid & 31, wid = tid >> 5;
    const int warpM = wid >> 2, warpN = wid & 3;
    const int lr = lane >> 2, lc = lane & 3;
    const int brow = blockIdx.y << 7, bcol = blockIdx.x << 8;

    const __half* Ab = A + (size_t)brow * K;
    const __half* Bbp = B + bcol;

    float acc[4][8][4];
    #pragma unroll
    for (int i = 0; i < 4; i++)
        #pragma unroll
        for (int j = 0; j < 8; j++)
            #pragma unroll
            for (int q = 0; q < 4; q++) acc[i][j][q] = 0.f;

    #define ISSUE(kt, s) do { \
        uint32_t as_ = cvs(smh + GA_H(s)); \
        uint32_t bs_ = cvs(smh + GB_H(s)); \
        _Pragma("unroll") \
        for (int it = 0; it < 2; it++) { \
            int idx = tid + it * 256; \
            int r = idx >> 2, c8 = (idx & 3) << 3; \
            cp16(as_ + (uint32_t)(r * LDAH + c8) * 2u, \
                 Ab + (size_t)r * K + (kt) * 32 + c8); \
        } \
        _Pragma("unroll") \
        for (int it = 0; it < 4; it++) { \
            int idx = tid + it * 256; \
            int r = idx >> 5, c8 = (idx & 31) << 3; \
            cp16(bs_ + (uint32_t)(r * LDBH + c8) * 2u, \
                 Bbp + (size_t)((kt) * 32 + r) * N + c8); \
        } \
        cp_commit(); \
    } while (0)

    const int NT = K >> 5;
    ISSUE(0, 0);

    const int aRow = lane & 15, aKoff = (lane & 16) ? 8 : 0;
    const int bRow = (lane & 7) + ((lane & 8) ? 8 : 0);
    const int bNoff = (lane & 16) ? 8 : 0;

    for (int kt = 0; kt < NT; kt++) {
        const int cur = kt & 1;
        if (kt + 1 < NT) { ISSUE(kt + 1, (kt + 1) & 1); cp_wait1(); }
        else cp_wait0();
        __syncthreads();

        const __half* Ac = smh + GA_H(cur);
        const __half* Bc = smh + GB_H(cur);
        #pragma unroll
        for (int ks = 0; ks < 2; ks++) {
            uint32_t af[4][4];
            #pragma unroll
            for (int mt = 0; mt < 4; mt++)
                ldsm4(af[mt], cvs(Ac + (warpM * 64 + mt * 16 + aRow) * LDAH
                                     + ks * 16 + aKoff));
            uint32_t bf[8][2];
            #pragma unroll
            for (int j2 = 0; j2 < 4; j2++) {
                uint32_t t[4];
                ldsm4t(t, cvs(Bc + (ks * 16 + bRow) * LDBH
                                 + warpN * 64 + j2 * 16 + bNoff));
                bf[2 * j2][0] = t[0]; bf[2 * j2][1] = t[1];
                bf[2 * j2 + 1][0] = t[2]; bf[2 * j2 + 1][1] = t[3];
            }
            #pragma unroll
            for (int mt = 0; mt < 4; mt++)
                #pragma unroll
                for (int nt = 0; nt < 8; nt++)
                    mma_f16(acc[mt][nt], af[mt], bf[nt]);
        }
        __syncthreads();
    }

    #pragma unroll
    for (int mt = 0; mt < 4; mt++)
        #pragma unroll
        for (int nt = 0; nt < 8; nt++) {
            int row = brow + warpM * 64 + mt * 16 + lr;
            int col = bcol + warpN * 64 + nt * 8 + 2 * lc;
            if constexpr (sizeof(TC) == 2) {
                *(__half2*)&C[(size_t)row * N + col] =
                    __floats2half2_rn(acc[mt][nt][0], acc[mt][nt][1]);
                *(__half2*)&C[(size_t)(row + 8) * N + col] =
                    __floats2half2_rn(acc[mt][nt][2], acc[mt][nt][3]);
            } else {
                *(float2*)&C[(size_t)row * N + col] =
                    make_float2(acc[mt][nt][0], acc[mt][nt][1]);
                *(float2*)&C[(size_t)(row + 8) * N + col] =
                    make_float2(acc[mt][nt][2], acc[mt][nt][3]);
            }
        }
    #undef ISSUE
}

// ---------------------------------------------------------------------------
// Causal flash attention (R11 proven config + LPT order): fp16 mma, register
// softmax (base-2), f16x2 exp, l via ones-mma. 128-key double-buffered stages
// (2 syncs + 1 wait per 128 keys), two 64-key sub-steps sharing registers.
// ---------------------------------------------------------------------------
#define LDFH 72
#define KBUF (128 * LDFH)       // one 128x64 tile (halfs)

__global__ __launch_bounds__(256)
void flash_f16(const __half* __restrict__ qkv, __half* __restrict__ out)
{
    extern __shared__ __half smf[];
    __half* Qstage = smf;

    // LPT order: first 24 blocks are qt=15 (all heads/batches), then qt=14, ...
    const int NQT = Tt / 256;                 // 16
    const int qt = NQT - 1 - ((int)blockIdx.x / (NHh * Bb));
    const int hb = (int)blockIdx.x % (NHh * Bb);
    const int h = hb % NHh, b = hb / NHh;

    const int tid = threadIdx.x;
    const int lane = tid & 31, w = tid >> 5;
    const int lr = lane >> 2, lc = lane & 3;
    const float NEG = -1e30f;
    const float qscale = 0.125f * 1.44269504089f;

    const int q0 = qt * 256;
    const size_t qrow0 = (size_t)(b * Tt + q0);
    const __half* qbase = qkv + qrow0 * C3 + h * HSs;

    {
        const __half* qr = qbase + (size_t)tid * C3;
        __half* qd = Qstage + tid * LDFH;
        #pragma unroll
        for (int c8 = 0; c8 < 64; c8 += 8) {
            uint4 u = *(const uint4*)(qr + c8);
            __half2* hp = (__half2*)&u;
            #pragma unroll
            for (int q = 0; q < 4; q++) {
                float2 f = __half22float2(hp[q]);
                hp[q] = __floats2half2_rn(f.x * qscale, f.y * qscale);
            }
            *(uint4*)(qd + c8) = u;
        }
    }
    __syncthreads();

    const int aRow = lane & 15, aKoff = (lane & 16) ? 8 : 0;
    uint32_t qf[2][4][4];
    #pragma unroll
    for (int mt = 0; mt < 2; mt++)
        #pragma unroll
        for (int ks = 0; ks < 4; ks++)
            ldsm4(qf[mt][ks], cvs(Qstage + (w * 32 + mt * 16 + aRow) * LDFH
                                     + ks * 16 + aKoff));
    __syncthreads();

    const int nIter = 2 * qt + 2;            // 128-key tiles
    const __half* kvb = qkv + (size_t)(b * Tt) * C3 + Cc + h * HSs;

    #define ISSUEF(jb_, s_) do { \
        const __half* kb_ = kvb + (size_t)(jb_) * 128 * C3; \
        uint32_t kd_ = cvs(smf + (s_) * 2 * KBUF); \
        uint32_t vd_ = kd_ + KBUF * 2; \
        _Pragma("unroll") \
        for (int it = 0; it < 4; it++) { \
            int idx = tid + it * 256; \
            int r = idx >> 3, c8 = (idx & 7) << 3; \
            size_t go = (size_t)r * C3 + c8; \
            uint32_t so = (uint32_t)(r * LDFH + c8) * 2u; \
            cp16(kd_ + so, kb_ + go); \
            cp16(vd_ + so, kb_ + Cc + go); \
        } \
        cp_commit(); \
    } while (0)

    ISSUEF(0, 0);

    float accO[2][8][4];
    float lAcc[2][4];
    #pragma unroll
    for (int mt = 0; mt < 2; mt++) {
        #pragma unroll
        for (int j = 0; j < 8; j++)
            #pragma unroll
            for (int q = 0; q < 4; q++) accO[mt][j][q] = 0.f;
        #pragma unroll
        for (int q = 0; q < 4; q++) lAcc[mt][q] = 0.f;
    }
    float mrun[2][2] = {{NEG, NEG}, {NEG, NEG}};
    const uint32_t ONES2 = 0x3C003C00u;
    const uint32_t onesB[2] = {ONES2, ONES2};

    const int kRow = (lane & 7) + ((lane & 8) ? 8 : 0);
    const int kOff = (lane & 16) ? 8 : 0;

    for (int jb = 0; jb < nIter; jb++) {
        const int cur = jb & 1;
        __half* Kt = smf + cur * 2 * KBUF;
        __half* Vt = Kt + KBUF;

        __syncthreads();
        int nxt = jb + 1 < nIter ? jb + 1 : jb;
        ISSUEF(nxt, (jb + 1) & 1);
        cp_wait1();
        __syncthreads();

        #pragma unroll
        for (int sub = 0; sub < 2; sub++) {
            const int kb64 = jb * 2 + sub;
            __half* Ks = Kt + sub * 64 * LDFH;
            __half* Vs = Vt + sub * 64 * LDFH;

            // ---- S = Q x K^T ----
            float sAcc[2][8][4];
            #pragma unroll
            for (int mt = 0; mt < 2; mt++)
                #pragma unroll
                for (int j = 0; j < 8; j++)
                    #pragma unroll
                    for (int q = 0; q < 4; q++) sAcc[mt][j][q] = 0.f;

            #pragma unroll
            for (int ks = 0; ks < 4; ks++) {
                uint32_t kf[8][2];
                #pragma unroll
                for (int j2 = 0; j2 < 4; j2++) {
                    uint32_t t[4];
                    ldsm4(t, cvs(Ks + (j2 * 16 + kRow) * LDFH + ks * 16 + kOff));
                    kf[2 * j2][0] = t[0]; kf[2 * j2][1] = t[2];
                    kf[2 * j2 + 1][0] = t[1]; kf[2 * j2 + 1][1] = t[3];
                }
                #pragma unroll
                for (int nj = 0; nj < 8; nj++) {
                    mma_f16(sAcc[0][nj], qf[0][ks], kf[nj]);
                    mma_f16(sAcc[1][nj], qf[1][ks], kf[nj]);
                }
            }

            // ---- mask + online softmax ----
            uint32_t paf[2][4][4];
            #pragma unroll
            for (int mt = 0; mt < 2; mt++) {
                const int rowA = q0 + w * 32 + mt * 16 + lr;
                const int rowB = rowA + 8;
                if (kb64 * 64 + 63 > q0 + w * 32 + mt * 16) {
                    #pragma unroll
                    for (int nj = 0; nj < 8; nj++) {
                        int col = kb64 * 64 + nj * 8 + 2 * lc;
                        if (col > rowA)     sAcc[mt][nj][0] = NEG;
                        if (col + 1 > rowA) sAcc[mt][nj][1] = NEG;
                        if (col > rowB)     sAcc[mt][nj][2] = NEG;
                        if (col + 1 > rowB) sAcc[mt][nj][3] = NEG;
                    }
                }

                float mxA = NEG, mxB = NEG;
                #pragma unroll
                for (int nj = 0; nj < 8; nj++) {
                    mxA = fmaxf(mxA, fmaxf(sAcc[mt][nj][0], sAcc[mt][nj][1]));
                    mxB = fmaxf(mxB, fmaxf(sAcc[mt][nj][2], sAcc[mt][nj][3]));
                }
                mxA = fmaxf(mxA, __shfl_xor_sync(0xffffffffu, mxA, 1));
                mxA = fmaxf(mxA, __shfl_xor_sync(0xffffffffu, mxA, 2));
                mxB = fmaxf(mxB, __shfl_xor_sync(0xffffffffu, mxB, 1));
                mxB = fmaxf(mxB, __shfl_xor_sync(0xffffffffu, mxB, 2));

                float mn0 = fmaxf(mrun[mt][0], mxA), mn1 = fmaxf(mrun[mt][1], mxB);
                float al0 = ex2(mrun[mt][0] - mn0), al1 = ex2(mrun[mt][1] - mn1);
                mrun[mt][0] = mn0; mrun[mt][1] = mn1;

                #pragma unroll
                for (int ks = 0; ks < 4; ks++) {
                    paf[mt][ks][0] = ex2h2(pk(sAcc[mt][2 * ks][0] - mn0,
                                              sAcc[mt][2 * ks][1] - mn0));
                    paf[mt][ks][1] = ex2h2(pk(sAcc[mt][2 * ks][2] - mn1,
                                              sAcc[mt][2 * ks][3] - mn1));
                    paf[mt][ks][2] = ex2h2(pk(sAcc[mt][2 * ks + 1][0] - mn0,
                                              sAcc[mt][2 * ks + 1][1] - mn0));
                    paf[mt][ks][3] = ex2h2(pk(sAcc[mt][2 * ks + 1][2] - mn1,
                                              sAcc[mt][2 * ks + 1][3] - mn1));
                }

                #pragma unroll
                for (int nj = 0; nj < 8; nj++) {
                    accO[mt][nj][0] *= al0; accO[mt][nj][1] *= al0;
                    accO[mt][nj][2] *= al1; accO[mt][nj][3] *= al1;
                }
                lAcc[mt][0] *= al0; lAcc[mt][1] *= al0;
                lAcc[mt][2] *= al1; lAcc[mt][3] *= al1;

                #pragma unroll
                for (int ks = 0; ks < 4; ks++)
                    mma_f16(lAcc[mt], paf[mt][ks], onesB);
            }

            // ---- O += P x V ----
            #pragma unroll
            for (int ks = 0; ks < 4; ks++) {
                uint32_t vf[8][2];
                #pragma unroll
                for (int j2 = 0; j2 < 4; j2++) {
                    uint32_t t[4];
                    ldsm4t(t, cvs(Vs + (ks * 16 + kRow) * LDFH + j2 * 16 + kOff));
                    vf[2 * j2][0] = t[0]; vf[2 * j2][1] = t[1];
                    vf[2 * j2 + 1][0] = t[2]; vf[2 * j2 + 1][1] = t[3];
                }
                #pragma unroll
                for (int nj = 0; nj < 8; nj++) {
                    mma_f16(accO[0][nj], paf[0][ks], vf[nj]);
                    mma_f16(accO[1][nj], paf[1][ks], vf[nj]);
                }
            }
        }
    }

    cp_wait0();

    __half* obase = out + qrow0 * Cc + h * HSs;
    #pragma unroll
    for (int mt = 0; mt < 2; mt++) {
        int r0 = w * 32 + mt * 16 + lr;
        float rl0 = 1.f / lAcc[mt][0], rl1 = 1.f / lAcc[mt][2];
        #pragma unroll
        for (int nj = 0; nj < 8; nj++) {
            int col = nj * 8 + 2 * lc;
            *(__half2*)(obase + (size_t)r0 * Cc + col) =
                __floats2half2_rn(accO[mt][nj][0] * rl0, accO[mt][nj][1] * rl0);
            *(__half2*)(obase + (size_t)(r0 + 8) * Cc + col) =
                __floats2half2_rn(accO[mt][nj][2] * rl1, accO[mt][nj][3] * rl1);
        }
    }
    #undef ISSUEF
}

// ---------------------------------------------------------------------------
extern "C" void kernel_launch(void* const* d_in, const int* in_sizes, int n_in,
                              void* d_out, int out_size)
{
    const float* x      = (const float*)d_in[0];
    const float* w_attn = (const float*)d_in[1];
    const float* w_proj = (const float*)d_in[2];
    float* out = (float*)d_out;

    __half *qkv, *att, *xh, *wa, *wp;
    cudaGetSymbolAddress((void**)&qkv, g_qkv);
    cudaGetSymbolAddress((void**)&att, g_att);
    cudaGetSymbolAddress((void**)&xh, g_xh);
    cudaGetSymbolAddress((void**)&wa, g_wa);
    cudaGetSymbolAddress((void**)&wp, g_wp);

    const int GEMM_SMEM = GEMM_SMEM_H * sizeof(__half);     // 54272 B
    const int FLASH_SMEM = 4 * KBUF * sizeof(__half);       // 73728 B
    cudaFuncSetAttribute(gemm_h16<__half>,
                         cudaFuncAttributeMaxDynamicSharedMemorySize, GEMM_SMEM);
    cudaFuncSetAttribute(gemm_h16<float>,
                         cudaFuncAttributeMaxDynamicSharedMemorySize, GEMM_SMEM);
    cudaFuncSetAttribute(flash_f16,
                         cudaFuncAttributeMaxDynamicSharedMemorySize, FLASH_SMEM);

    // 0) fp32 -> fp16 conversions (single launch)
    {
        int n0 = BT * Cc / 4, n1 = Cc * C3 / 4, n2 = Cc * Cc / 4;
        int nt = n0 + n1 + n2;
        f2h3<<<(nt + 255) / 256, 256>>>(x, xh, n0, w_attn, wa, n1, w_proj, wp, n2);
    }
    // 1) QKV projection (all-half, 128x256 tiles, double-buffered)
    gemm_h16<__half><<<dim3(C3 / 256, BT / 128), 256, GEMM_SMEM>>>(
        xh, wa, qkv, BT, C3, Cc);
    // 2) Causal flash attention (128-key double-buffered stages, LPT order)
    flash_f16<<<(Tt / 256) * NHh * Bb, 256, FLASH_SMEM>>>(qkv, att);
    // 3) Output projection (half in, float out)
    gemm_h16<float><<<dim3(Cc / 256, BT / 128), 256, GEMM_SMEM>>>(
        att, wp, out, BT, Cc, Cc);
}

// round 15
// speedup vs baseline: 1.5183x; 1.0305x over previous
#include <cuda_runtime.h>
#include <cuda_fp16.h>
#include <math.h>
#include <stdint.h>

#define Bb 2
#define Tt 4096
#define Cc 768
#define NHh 12
#define HSs 64
#define BT (Bb*Tt)
#define C3 (3*Cc)

__device__ __half g_qkv[(size_t)BT * C3];   // [B*T, 3C] fp16
__device__ __half g_att[(size_t)BT * Cc];   // [B*T, C]  fp16
__device__ __half g_xh [(size_t)BT * Cc];   // x in fp16
__device__ __half g_wa [(size_t)Cc * C3];   // w_attn fp16
__device__ __half g_wp [(size_t)Cc * Cc];   // w_proj fp16

__device__ __forceinline__ uint32_t h2u(__half2 h) {
    return *reinterpret_cast<uint32_t*>(&h);
}
__device__ __forceinline__ uint32_t pk(float a, float b) {
    __half2 h = __floats2half2_rn(a, b);
    return h2u(h);
}
__device__ __forceinline__ float ex2(float x) {
    float r;
    asm("ex2.approx.ftz.f32 %0, %1;" : "=f"(r) : "f"(x));
    return r;
}
__device__ __forceinline__ uint32_t ex2h2(uint32_t x) {
    uint32_t r;
    asm("ex2.approx.f16x2 %0, %1;" : "=r"(r) : "r"(x));
    return r;
}
__device__ __forceinline__ void cp16(uint32_t dst, const void* src) {
    asm volatile("cp.async.cg.shared.global [%0], [%1], 16;" :: "r"(dst), "l"(src));
}
__device__ __forceinline__ void cp_commit() { asm volatile("cp.async.commit_group;"); }
__device__ __forceinline__ void cp_wait1()  { asm volatile("cp.async.wait_group 1;"); }
__device__ __forceinline__ void cp_wait0()  { asm volatile("cp.async.wait_group 0;"); }

__device__ __forceinline__ void mma_f16(float c[4], const uint32_t a[4], const uint32_t b[2]) {
    asm volatile(
        "mma.sync.aligned.m16n8k16.row.col.f32.f16.f16.f32 "
        "{%0,%1,%2,%3},{%4,%5,%6,%7},{%8,%9},{%0,%1,%2,%3};"
        : "+f"(c[0]), "+f"(c[1]), "+f"(c[2]), "+f"(c[3])
        : "r"(a[0]), "r"(a[1]), "r"(a[2]), "r"(a[3]), "r"(b[0]), "r"(b[1]));
}
__device__ __forceinline__ void ldsm4(uint32_t r[4], uint32_t saddr) {
    asm volatile("ldmatrix.sync.aligned.m8n8.x4.shared.b16 {%0,%1,%2,%3}, [%4];"
                 : "=r"(r[0]), "=r"(r[1]), "=r"(r[2]), "=r"(r[3]) : "r"(saddr));
}
__device__ __forceinline__ void ldsm4t(uint32_t r[4], uint32_t saddr) {
    asm volatile("ldmatrix.sync.aligned.m8n8.x4.trans.shared.b16 {%0,%1,%2,%3}, [%4];"
                 : "=r"(r[0]), "=r"(r[1]), "=r"(r[2]), "=r"(r[3]) : "r"(saddr));
}
__device__ __forceinline__ uint32_t cvs(const void* p) {
    return (uint32_t)__cvta_generic_to_shared(p);
}

// ---------------------------------------------------------------------------
// fp32 -> fp16 bulk convert, all three tensors in one launch
// ---------------------------------------------------------------------------
__global__ void f2h3(const float* __restrict__ s0, __half* __restrict__ d0, int n0,
                     const float* __restrict__ s1, __half* __restrict__ d1, int n1,
                     const float* __restrict__ s2, __half* __restrict__ d2, int n2)
{
    int i = blockIdx.x * blockDim.x + threadIdx.x;
    const float* s; __half* d; int j;
    if (i < n0)           { s = s0; d = d0; j = i; }
    else if (i < n0 + n1) { s = s1; d = d1; j = i - n0; }
    else if (i < n0 + n1 + n2) { s = s2; d = d2; j = i - n0 - n1; }
    else return;
    float4 v = *(const float4*)(s + (size_t)j * 4);
    uint2 u;
    u.x = pk(v.x, v.y);
    u.y = pk(v.z, v.w);
    *(uint2*)(d + (size_t)j * 4) = u;
}

// ---------------------------------------------------------------------------
// All-half GEMM, N-tile templated: CTA 128xBN, 8 warps (2x4), warp 64x(BN/4).
// kc=32, double-buffered cp.async, 2 syncs per chunk. BN in {128, 256}.
// ---------------------------------------------------------------------------
#define LDAH 40

template <int BN, typename TC>
__global__ __launch_bounds__(256)
void gemm_h16(const __half* __restrict__ A, const __half* __restrict__ B,
              TC* __restrict__ C, int M, int N, int K)
{
    constexpr int LDBH = BN + 8;
    constexpr int NTIL = BN / 32;     // n-tiles per warp (8 or 4)
    constexpr int BIT  = BN / 64;     // B cp16 iters per thread (4 or 2)
    constexpr int GA0 = 0, GA1 = 128 * LDAH;
    constexpr int GB0 = 2 * 128 * LDAH, GB1 = GB0 + 32 * LDBH;

    extern __shared__ __half smh[];

    const int tid = threadIdx.x;
    const int lane = tid & 31, wid = tid >> 5;
    const int warpM = wid >> 2, warpN = wid & 3;
    const int lr = lane >> 2, lc = lane & 3;
    const int brow = blockIdx.y << 7;
    const int bcol = blockIdx.x * BN;

    const __half* Ab = A + (size_t)brow * K;
    const __half* Bbp = B + bcol;

    float acc[4][NTIL][4];
    #pragma unroll
    for (int i = 0; i < 4; i++)
        #pragma unroll
        for (int j = 0; j < NTIL; j++)
            #pragma unroll
            for (int q = 0; q < 4; q++) acc[i][j][q] = 0.f;

    #define ISSUE(kt, s) do { \
        uint32_t as_ = cvs(smh + ((s) ? GA1 : GA0)); \
        uint32_t bs_ = cvs(smh + ((s) ? GB1 : GB0)); \
        _Pragma("unroll") \
        for (int it = 0; it < 2; it++) { \
            int idx = tid + it * 256; \
            int r = idx >> 2, c8 = (idx & 3) << 3; \
            cp16(as_ + (uint32_t)(r * LDAH + c8) * 2u, \
                 Ab + (size_t)r * K + (kt) * 32 + c8); \
        } \
        _Pragma("unroll") \
        for (int it = 0; it < BIT; it++) { \
            int idx = tid + it * 256; \
            int r = idx / (BN / 8), c8 = (idx % (BN / 8)) << 3; \
            cp16(bs_ + (uint32_t)(r * LDBH + c8) * 2u, \
                 Bbp + (size_t)((kt) * 32 + r) * N + c8); \
        } \
        cp_commit(); \
    } while (0)

    const int NT = K >> 5;
    ISSUE(0, 0);

    const int aRow = lane & 15, aKoff = (lane & 16) ? 8 : 0;
    const int bRow = (lane & 7) + ((lane & 8) ? 8 : 0);
    const int bNoff = (lane & 16) ? 8 : 0;

    for (int kt = 0; kt < NT; kt++) {
        const int cur = kt & 1;
        if (kt + 1 < NT) { ISSUE(kt + 1, (kt + 1) & 1); cp_wait1(); }
        else cp_wait0();
        __syncthreads();

        const __half* Ac = smh + (cur ? GA1 : GA0);
        const __half* Bc = smh + (cur ? GB1 : GB0);
        #pragma unroll
        for (int ks = 0; ks < 2; ks++) {
            uint32_t af[4][4];
            #pragma unroll
            for (int mt = 0; mt < 4; mt++)
                ldsm4(af[mt], cvs(Ac + (warpM * 64 + mt * 16 + aRow) * LDAH
                                     + ks * 16 + aKoff));
            uint32_t bf[NTIL][2];
            #pragma unroll
            for (int j2 = 0; j2 < NTIL / 2; j2++) {
                uint32_t t[4];
                ldsm4t(t, cvs(Bc + (ks * 16 + bRow) * LDBH
                                 + warpN * (BN / 4) + j2 * 16 + bNoff));
                bf[2 * j2][0] = t[0]; bf[2 * j2][1] = t[1];
                bf[2 * j2 + 1][0] = t[2]; bf[2 * j2 + 1][1] = t[3];
            }
            #pragma unroll
            for (int mt = 0; mt < 4; mt++)
                #pragma unroll
                for (int nt = 0; nt < NTIL; nt++)
                    mma_f16(acc[mt][nt], af[mt], bf[nt]);
        }
        __syncthreads();
    }

    #pragma unroll
    for (int mt = 0; mt < 4; mt++)
        #pragma unroll
        for (int nt = 0; nt < NTIL; nt++) {
            int row = brow + warpM * 64 + mt * 16 + lr;
            int col = bcol + warpN * (BN / 4) + nt * 8 + 2 * lc;
            if constexpr (sizeof(TC) == 2) {
                *(__half2*)&C[(size_t)row * N + col] =
                    __floats2half2_rn(acc[mt][nt][0], acc[mt][nt][1]);
                *(__half2*)&C[(size_t)(row + 8) * N + col] =
                    __floats2half2_rn(acc[mt][nt][2], acc[mt][nt][3]);
            } else {
                *(float2*)&C[(size_t)row * N + col] =
                    make_float2(acc[mt][nt][0], acc[mt][nt][1]);
                *(float2*)&C[(size_t)(row + 8) * N + col] =
                    make_float2(acc[mt][nt][2], acc[mt][nt][3]);
            }
        }
    #undef ISSUE
}

// ---------------------------------------------------------------------------
// Causal flash attention (R14 winner, verbatim): fp16 mma, register softmax
// (base-2), f16x2 exp, l via ones-mma. 128-key double-buffered stages,
// two 64-key sub-steps sharing registers, LPT heavy-first 1-D grid.
// ---------------------------------------------------------------------------
#define LDFH 72
#define KBUF (128 * LDFH)       // one 128x64 tile (halfs)

__global__ __launch_bounds__(256)
void flash_f16(const __half* __restrict__ qkv, __half* __restrict__ out)
{
    extern __shared__ __half smf[];
    __half* Qstage = smf;

    const int NQT = Tt / 256;                 // 16
    const int qt = NQT - 1 - ((int)blockIdx.x / (NHh * Bb));
    const int hb = (int)blockIdx.x % (NHh * Bb);
    const int h = hb % NHh, b = hb / NHh;

    const int tid = threadIdx.x;
    const int lane = tid & 31, w = tid >> 5;
    const int lr = lane >> 2, lc = lane & 3;
    const float NEG = -1e30f;
    const float qscale = 0.125f * 1.44269504089f;

    const int q0 = qt * 256;
    const size_t qrow0 = (size_t)(b * Tt + q0);
    const __half* qbase = qkv + qrow0 * C3 + h * HSs;

    {
        const __half* qr = qbase + (size_t)tid * C3;
        __half* qd = Qstage + tid * LDFH;
        #pragma unroll
        for (int c8 = 0; c8 < 64; c8 += 8) {
            uint4 u = *(const uint4*)(qr + c8);
            __half2* hp = (__half2*)&u;
            #pragma unroll
            for (int q = 0; q < 4; q++) {
                float2 f = __half22float2(hp[q]);
                hp[q] = __floats2half2_rn(f.x * qscale, f.y * qscale);
            }
            *(uint4*)(qd + c8) = u;
        }
    }
    __syncthreads();

    const int aRow = lane & 15, aKoff = (lane & 16) ? 8 : 0;
    uint32_t qf[2][4][4];
    #pragma unroll
    for (int mt = 0; mt < 2; mt++)
        #pragma unroll
        for (int ks = 0; ks < 4; ks++)
            ldsm4(qf[mt][ks], cvs(Qstage + (w * 32 + mt * 16 + aRow) * LDFH
                                     + ks * 16 + aKoff));
    __syncthreads();

    const int nIter = 2 * qt + 2;            // 128-key tiles
    const __half* kvb = qkv + (size_t)(b * Tt) * C3 + Cc + h * HSs;

    #define ISSUEF(jb_, s_) do { \
        const __half* kb_ = kvb + (size_t)(jb_) * 128 * C3; \
        uint32_t kd_ = cvs(smf + (s_) * 2 * KBUF); \
        uint32_t vd_ = kd_ + KBUF * 2; \
        _Pragma("unroll") \
        for (int it = 0; it < 4; it++) { \
            int idx = tid + it * 256; \
            int r = idx >> 3, c8 = (idx & 7) << 3; \
            size_t go = (size_t)r * C3 + c8; \
            uint32_t so = (uint32_t)(r * LDFH + c8) * 2u; \
            cp16(kd_ + so, kb_ + go); \
            cp16(vd_ + so, kb_ + Cc + go); \
        } \
        cp_commit(); \
    } while (0)

    ISSUEF(0, 0);

    float accO[2][8][4];
    float lAcc[2][4];
    #pragma unroll
    for (int mt = 0; mt < 2; mt++) {
        #pragma unroll
        for (int j = 0; j < 8; j++)
            #pragma unroll
            for (int q = 0; q < 4; q++) accO[mt][j][q] = 0.f;
        #pragma unroll
        for (int q = 0; q < 4; q++) lAcc[mt][q] = 0.f;
    }
    float mrun[2][2] = {{NEG, NEG}, {NEG, NEG}};
    const uint32_t ONES2 = 0x3C003C00u;
    const uint32_t onesB[2] = {ONES2, ONES2};

    const int kRow = (lane & 7) + ((lane & 8) ? 8 : 0);
    const int kOff = (lane & 16) ? 8 : 0;

    for (int jb = 0; jb < nIter; jb++) {
        const int cur = jb & 1;
        __half* Kt = smf + cur * 2 * KBUF;
        __half* Vt = Kt + KBUF;

        __syncthreads();
        int nxt = jb + 1 < nIter ? jb + 1 : jb;
        ISSUEF(nxt, (jb + 1) & 1);
        cp_wait1();
        __syncthreads();

        #pragma unroll
        for (int sub = 0; sub < 2; sub++) {
            const int kb64 = jb * 2 + sub;
            __half* Ks = Kt + sub * 64 * LDFH;
            __half* Vs = Vt + sub * 64 * LDFH;

            // ---- S = Q x K^T ----
            float sAcc[2][8][4];
            #pragma unroll
            for (int mt = 0; mt < 2; mt++)
                #pragma unroll
                for (int j = 0; j < 8; j++)
                    #pragma unroll
                    for (int q = 0; q < 4; q++) sAcc[mt][j][q] = 0.f;

            #pragma unroll
            for (int ks = 0; ks < 4; ks++) {
                uint32_t kf[8][2];
                #pragma unroll
                for (int j2 = 0; j2 < 4; j2++) {
                    uint32_t t[4];
                    ldsm4(t, cvs(Ks + (j2 * 16 + kRow) * LDFH + ks * 16 + kOff));
                    kf[2 * j2][0] = t[0]; kf[2 * j2][1] = t[2];
                    kf[2 * j2 + 1][0] = t[1]; kf[2 * j2 + 1][1] = t[3];
                }
                #pragma unroll
                for (int nj = 0; nj < 8; nj++) {
                    mma_f16(sAcc[0][nj], qf[0][ks], kf[nj]);
                    mma_f16(sAcc[1][nj], qf[1][ks], kf[nj]);
                }
            }

            // ---- mask + online softmax ----
            uint32_t paf[2][4][4];
            #pragma unroll
            for (int mt = 0; mt < 2; mt++) {
                const int rowA = q0 + w * 32 + mt * 16 + lr;
                const int rowB = rowA + 8;
                if (kb64 * 64 + 63 > q0 + w * 32 + mt * 16) {
                    #pragma unroll
                    for (int nj = 0; nj < 8; nj++) {
                        int col = kb64 * 64 + nj * 8 + 2 * lc;
                        if (col > rowA)     sAcc[mt][nj][0] = NEG;
                        if (col + 1 > rowA) sAcc[mt][nj][1] = NEG;
                        if (col > rowB)     sAcc[mt][nj][2] = NEG;
                        if (col + 1 > rowB) sAcc[mt][nj][3] = NEG;
                    }
                }

                float mxA = NEG, mxB = NEG;
                #pragma unroll
                for (int nj = 0; nj < 8; nj++) {
                    mxA = fmaxf(mxA, fmaxf(sAcc[mt][nj][0], sAcc[mt][nj][1]));
                    mxB = fmaxf(mxB, fmaxf(sAcc[mt][nj][2], sAcc[mt][nj][3]));
                }
                mxA = fmaxf(mxA, __shfl_xor_sync(0xffffffffu, mxA, 1));
                mxA = fmaxf(mxA, __shfl_xor_sync(0xffffffffu, mxA, 2));
                mxB = fmaxf(mxB, __shfl_xor_sync(0xffffffffu, mxB, 1));
                mxB = fmaxf(mxB, __shfl_xor_sync(0xffffffffu, mxB, 2));

                float mn0 = fmaxf(mrun[mt][0], mxA), mn1 = fmaxf(mrun[mt][1], mxB);
                float al0 = ex2(mrun[mt][0] - mn0), al1 = ex2(mrun[mt][1] - mn1);
                mrun[mt][0] = mn0; mrun[mt][1] = mn1;

                #pragma unroll
                for (int ks = 0; ks < 4; ks++) {
                    paf[mt][ks][0] = ex2h2(pk(sAcc[mt][2 * ks][0] - mn0,
                                              sAcc[mt][2 * ks][1] - mn0));
                    paf[mt][ks][1] = ex2h2(pk(sAcc[mt][2 * ks][2] - mn1,
                                              sAcc[mt][2 * ks][3] - mn1));
                    paf[mt][ks][2] = ex2h2(pk(sAcc[mt][2 * ks + 1][0] - mn0,
                                              sAcc[mt][2 * ks + 1][1] - mn0));
                    paf[mt][ks][3] = ex2h2(pk(sAcc[mt][2 * ks + 1][2] - mn1,
                                              sAcc[mt][2 * ks + 1][3] - mn1));
                }

                #pragma unroll
                for (int nj = 0; nj < 8; nj++) {
                    accO[mt][nj][0] *= al0; accO[mt][nj][1] *= al0;
                    accO[mt][nj][2] *= al1; accO[mt][nj][3] *= al1;
                }
                lAcc[mt][0] *= al0; lAcc[mt][1] *= al0;
                lAcc[mt][2] *= al1; lAcc[mt][3] *= al1;

                #pragma unroll
                for (int ks = 0; ks < 4; ks++)
                    mma_f16(lAcc[mt], paf[mt][ks], onesB);
            }

            // ---- O += P x V ----
            #pragma unroll
            for (int ks = 0; ks < 4; ks++) {
                uint32_t vf[8][2];
                #pragma unroll
                for (int j2 = 0; j2 < 4; j2++) {
                    uint32_t t[4];
                    ldsm4t(t, cvs(Vs + (ks * 16 + kRow) * LDFH + j2 * 16 + kOff));
                    vf[2 * j2][0] = t[0]; vf[2 * j2][1] = t[1];
                    vf[2 * j2 + 1][0] = t[2]; vf[2 * j2 + 1][1] = t[3];
                }
                #pragma unroll
                for (int nj = 0; nj < 8; nj++) {
                    mma_f16(accO[0][nj], paf[0][ks], vf[nj]);
                    mma_f16(accO[1][nj], paf[1][ks], vf[nj]);
                }
            }
        }
    }

    cp_wait0();

    __half* obase = out + qrow0 * Cc + h * HSs;
    #pragma unroll
    for (int mt = 0; mt < 2; mt++) {
        int r0 = w * 32 + mt * 16 + lr;
        float rl0 = 1.f / lAcc[mt][0], rl1 = 1.f / lAcc[mt][2];
        #pragma unroll
        for (int nj = 0; nj < 8; nj++) {
            int col = nj * 8 + 2 * lc;
            *(__half2*)(obase + (size_t)r0 * Cc + col) =
                __floats2half2_rn(accO[mt][nj][0] * rl0, accO[mt][nj][1] * rl0);
            *(__half2*)(obase + (size_t)(r0 + 8) * Cc + col) =
                __floats2half2_rn(accO[mt][nj][2] * rl1, accO[mt][nj][3] * rl1);
        }
    }
    #undef ISSUEF
}

// ---------------------------------------------------------------------------
extern "C" void kernel_launch(void* const* d_in, const int* in_sizes, int n_in,
                              void* d_out, int out_size)
{
    const float* x      = (const float*)d_in[0];
    const float* w_attn = (const float*)d_in[1];
    const float* w_proj = (const float*)d_in[2];
    float* out = (float*)d_out;

    __half *qkv, *att, *xh, *wa, *wp;
    cudaGetSymbolAddress((void**)&qkv, g_qkv);
    cudaGetSymbolAddress((void**)&att, g_att);
    cudaGetSymbolAddress((void**)&xh, g_xh);
    cudaGetSymbolAddress((void**)&wa, g_wa);
    cudaGetSymbolAddress((void**)&wp, g_wp);

    const int GEMM_SMEM1 = (2 * 128 * LDAH + 2 * 32 * (256 + 8)) * (int)sizeof(__half); // 54272
    const int GEMM_SMEM2 = (2 * 128 * LDAH + 2 * 32 * (128 + 8)) * (int)sizeof(__half); // 37888
    const int FLASH_SMEM = 4 * KBUF * (int)sizeof(__half);                              // 73728
    cudaFuncSetAttribute(gemm_h16<256, __half>,
                         cudaFuncAttributeMaxDynamicSharedMemorySize, GEMM_SMEM1);
    cudaFuncSetAttribute(gemm_h16<128, float>,
                         cudaFuncAttributeMaxDynamicSharedMemorySize, GEMM_SMEM2);
    cudaFuncSetAttribute(flash_f16,
                         cudaFuncAttributeMaxDynamicSharedMemorySize, FLASH_SMEM);

    // 0) fp32 -> fp16 conversions (single launch)
    {
        int n0 = BT * Cc / 4, n1 = Cc * C3 / 4, n2 = Cc * Cc / 4;
        int nt = n0 + n1 + n2;
        f2h3<<<(nt + 255) / 256, 256>>>(x, xh, n0, w_attn, wa, n1, w_proj, wp, n2);
    }
    // 1) QKV projection (128x256 tiles, 576 CTAs = 3.9 waves)
    gemm_h16<256, __half><<<dim3(C3 / 256, BT / 128), 256, GEMM_SMEM1>>>(
        xh, wa, qkv, BT, C3, Cc);
    // 2) Causal flash attention (128-key double-buffered stages, LPT order)
    flash_f16<<<(Tt / 256) * NHh * Bb, 256, FLASH_SMEM>>>(qkv, att);
    // 3) Output projection (128x128 tiles, 384 CTAs = 2.6 waves)
    gemm_h16<128, float><<<dim3(Cc / 128, BT / 128), 256, GEMM_SMEM2>>>(
        att, wp, out, BT, Cc, Cc);
}

// round 16
// speedup vs baseline: 1.5306x; 1.0081x over previous
#include <cuda_runtime.h>
#include <cuda_fp16.h>
#include <math.h>
#include <stdint.h>

#define Bb 2
#define Tt 4096
#define Cc 768
#define NHh 12
#define HSs 64
#define BT (Bb*Tt)
#define C3 (3*Cc)

__device__ __half g_qkv[(size_t)BT * C3];   // [B*T, 3C] fp16
__device__ __half g_att[(size_t)BT * Cc];   // [B*T, C]  fp16
__device__ __half g_xh [(size_t)BT * Cc];   // x in fp16
__device__ __half g_wa [(size_t)Cc * C3];   // w_attn fp16
__device__ __half g_wp [(size_t)Cc * Cc];   // w_proj fp16

__device__ __forceinline__ uint32_t h2u(__half2 h) {
    return *reinterpret_cast<uint32_t*>(&h);
}
__device__ __forceinline__ uint32_t pk(float a, float b) {
    __half2 h = __floats2half2_rn(a, b);
    return h2u(h);
}
__device__ __forceinline__ float ex2(float x) {
    float r;
    asm("ex2.approx.ftz.f32 %0, %1;" : "=f"(r) : "f"(x));
    return r;
}
__device__ __forceinline__ uint32_t ex2h2(uint32_t x) {
    uint32_t r;
    asm("ex2.approx.f16x2 %0, %1;" : "=r"(r) : "r"(x));
    return r;
}
__device__ __forceinline__ void cp16(uint32_t dst, const void* src) {
    asm volatile("cp.async.cg.shared.global [%0], [%1], 16;" :: "r"(dst), "l"(src));
}
__device__ __forceinline__ void cp_commit() { asm volatile("cp.async.commit_group;"); }
__device__ __forceinline__ void cp_wait1()  { asm volatile("cp.async.wait_group 1;"); }
__device__ __forceinline__ void cp_wait0()  { asm volatile("cp.async.wait_group 0;"); }

__device__ __forceinline__ void mma_f16(float c[4], const uint32_t a[4], const uint32_t b[2]) {
    asm volatile(
        "mma.sync.aligned.m16n8k16.row.col.f32.f16.f16.f32 "
        "{%0,%1,%2,%3},{%4,%5,%6,%7},{%8,%9},{%0,%1,%2,%3};"
        : "+f"(c[0]), "+f"(c[1]), "+f"(c[2]), "+f"(c[3])
        : "r"(a[0]), "r"(a[1]), "r"(a[2]), "r"(a[3]), "r"(b[0]), "r"(b[1]));
}
__device__ __forceinline__ void ldsm4(uint32_t r[4], uint32_t saddr) {
    asm volatile("ldmatrix.sync.aligned.m8n8.x4.shared.b16 {%0,%1,%2,%3}, [%4];"
                 : "=r"(r[0]), "=r"(r[1]), "=r"(r[2]), "=r"(r[3]) : "r"(saddr));
}
__device__ __forceinline__ void ldsm4t(uint32_t r[4], uint32_t saddr) {
    asm volatile("ldmatrix.sync.aligned.m8n8.x4.trans.shared.b16 {%0,%1,%2,%3}, [%4];"
                 : "=r"(r[0]), "=r"(r[1]), "=r"(r[2]), "=r"(r[3]) : "r"(saddr));
}
__device__ __forceinline__ uint32_t cvs(const void* p) {
    return (uint32_t)__cvta_generic_to_shared(p);
}

// ---------------------------------------------------------------------------
// fp32 -> fp16 bulk convert, all three tensors in one launch
// ---------------------------------------------------------------------------
__global__ void f2h3(const float* __restrict__ s0, __half* __restrict__ d0, int n0,
                     const float* __restrict__ s1, __half* __restrict__ d1, int n1,
                     const float* __restrict__ s2, __half* __restrict__ d2, int n2)
{
    int i = blockIdx.x * blockDim.x + threadIdx.x;
    const float* s; __half* d; int j;
    if (i < n0)           { s = s0; d = d0; j = i; }
    else if (i < n0 + n1) { s = s1; d = d1; j = i - n0; }
    else if (i < n0 + n1 + n2) { s = s2; d = d2; j = i - n0 - n1; }
    else return;
    float4 v = *(const float4*)(s + (size_t)j * 4);
    uint2 u;
    u.x = pk(v.x, v.y);
    u.y = pk(v.z, v.w);
    *(uint2*)(d + (size_t)j * 4) = u;
}

// ---------------------------------------------------------------------------
// All-half GEMM, N-tile templated: CTA 128xBN, 8 warps (2x4), warp 64x(BN/4).
// kc=64 (4 k-steps of 16), double-buffered cp.async, 2 syncs per chunk.
// ---------------------------------------------------------------------------
#define LDAH 72   // 64+8: rows 144B apart, ≡16 mod 128 -> ldsm conflict-free

template <int BN, typename TC>
__global__ __launch_bounds__(256)
void gemm_h16(const __half* __restrict__ A, const __half* __restrict__ B,
              TC* __restrict__ C, int M, int N, int K)
{
    constexpr int LDBH = BN + 8;
    constexpr int NTIL = BN / 32;     // n-tiles per warp
    constexpr int BIT  = BN / 32;     // B cp16 iters per thread (64 rows x BN)
    constexpr int GA0 = 0, GA1 = 128 * LDAH;
    constexpr int GB0 = 2 * 128 * LDAH, GB1 = GB0 + 64 * LDBH;

    extern __shared__ __half smh[];

    const int tid = threadIdx.x;
    const int lane = tid & 31, wid = tid >> 5;
    const int warpM = wid >> 2, warpN = wid & 3;
    const int lr = lane >> 2, lc = lane & 3;
    const int brow = blockIdx.y << 7;
    const int bcol = blockIdx.x * BN;

    const __half* Ab = A + (size_t)brow * K;
    const __half* Bbp = B + bcol;

    float acc[4][NTIL][4];
    #pragma unroll
    for (int i = 0; i < 4; i++)
        #pragma unroll
        for (int j = 0; j < NTIL; j++)
            #pragma unroll
            for (int q = 0; q < 4; q++) acc[i][j][q] = 0.f;

    // A tile: 128 x 64 halfs = 1024 cp16 (4/thread). B tile: 64 x BN.
    #define ISSUE(kt, s) do { \
        uint32_t as_ = cvs(smh + ((s) ? GA1 : GA0)); \
        uint32_t bs_ = cvs(smh + ((s) ? GB1 : GB0)); \
        _Pragma("unroll") \
        for (int it = 0; it < 4; it++) { \
            int idx = tid + it * 256; \
            int r = idx >> 3, c8 = (idx & 7) << 3; \
            cp16(as_ + (uint32_t)(r * LDAH + c8) * 2u, \
                 Ab + (size_t)r * K + (kt) * 64 + c8); \
        } \
        _Pragma("unroll") \
        for (int it = 0; it < BIT; it++) { \
            int idx = tid + it * 256; \
            int r = idx / (BN / 8), c8 = (idx % (BN / 8)) << 3; \
            cp16(bs_ + (uint32_t)(r * LDBH + c8) * 2u, \
                 Bbp + (size_t)((kt) * 64 + r) * N + c8); \
        } \
        cp_commit(); \
    } while (0)

    const int NT = K >> 6;   // kc = 64
    ISSUE(0, 0);

    const int aRow = lane & 15, aKoff = (lane & 16) ? 8 : 0;
    const int bRow = (lane & 7) + ((lane & 8) ? 8 : 0);
    const int bNoff = (lane & 16) ? 8 : 0;

    for (int kt = 0; kt < NT; kt++) {
        const int cur = kt & 1;
        if (kt + 1 < NT) { ISSUE(kt + 1, (kt + 1) & 1); cp_wait1(); }
        else cp_wait0();
        __syncthreads();

        const __half* Ac = smh + (cur ? GA1 : GA0);
        const __half* Bc = smh + (cur ? GB1 : GB0);
        #pragma unroll
        for (int ks = 0; ks < 4; ks++) {
            uint32_t af[4][4];
            #pragma unroll
            for (int mt = 0; mt < 4; mt++)
                ldsm4(af[mt], cvs(Ac + (warpM * 64 + mt * 16 + aRow) * LDAH
                                     + ks * 16 + aKoff));
            uint32_t bf[NTIL][2];
            #pragma unroll
            for (int j2 = 0; j2 < NTIL / 2; j2++) {
                uint32_t t[4];
                ldsm4t(t, cvs(Bc + (ks * 16 + bRow) * LDBH
                                 + warpN * (BN / 4) + j2 * 16 + bNoff));
                bf[2 * j2][0] = t[0]; bf[2 * j2][1] = t[1];
                bf[2 * j2 + 1][0] = t[2]; bf[2 * j2 + 1][1] = t[3];
            }
            #pragma unroll
            for (int mt = 0; mt < 4; mt++)
                #pragma unroll
                for (int nt = 0; nt < NTIL; nt++)
                    mma_f16(acc[mt][nt], af[mt], bf[nt]);
        }
        __syncthreads();
    }

    #pragma unroll
    for (int mt = 0; mt < 4; mt++)
        #pragma unroll
        for (int nt = 0; nt < NTIL; nt++) {
            int row = brow + warpM * 64 + mt * 16 + lr;
            int col = bcol + warpN * (BN / 4) + nt * 8 + 2 * lc;
            if constexpr (sizeof(TC) == 2) {
                *(__half2*)&C[(size_t)row * N + col] =
                    __floats2half2_rn(acc[mt][nt][0], acc[mt][nt][1]);
                *(__half2*)&C[(size_t)(row + 8) * N + col] =
                    __floats2half2_rn(acc[mt][nt][2], acc[mt][nt][3]);
            } else {
                *(float2*)&C[(size_t)row * N + col] =
                    make_float2(acc[mt][nt][0], acc[mt][nt][1]);
                *(float2*)&C[(size_t)(row + 8) * N + col] =
                    make_float2(acc[mt][nt][2], acc[mt][nt][3]);
            }
        }
    #undef ISSUE
}

// ---------------------------------------------------------------------------
// Causal flash attention: fp16 mma, register softmax (base-2), f16x2 exp,
// l via ones-mma. 256-key double-buffered stages (2 syncs + 1 wait per 256
// keys), four 64-key sub-steps sharing registers. LPT heavy-first 1-D grid.
// ---------------------------------------------------------------------------
#define LDFH 72
#define KBUF (256 * LDFH)       // one 256x64 tile (halfs)

__global__ __launch_bounds__(256)
void flash_f16(const __half* __restrict__ qkv, __half* __restrict__ out)
{
    extern __shared__ __half smf[];
    __half* Qstage = smf;

    const int NQT = Tt / 256;                 // 16
    const int qt = NQT - 1 - ((int)blockIdx.x / (NHh * Bb));
    const int hb = (int)blockIdx.x % (NHh * Bb);
    const int h = hb % NHh, b = hb / NHh;

    const int tid = threadIdx.x;
    const int lane = tid & 31, w = tid >> 5;
    const int lr = lane >> 2, lc = lane & 3;
    const float NEG = -1e30f;
    const float qscale = 0.125f * 1.44269504089f;

    const int q0 = qt * 256;
    const size_t qrow0 = (size_t)(b * Tt + q0);
    const __half* qbase = qkv + qrow0 * C3 + h * HSs;

    {
        const __half* qr = qbase + (size_t)tid * C3;
        __half* qd = Qstage + tid * LDFH;
        #pragma unroll
        for (int c8 = 0; c8 < 64; c8 += 8) {
            uint4 u = *(const uint4*)(qr + c8);
            __half2* hp = (__half2*)&u;
            #pragma unroll
            for (int q = 0; q < 4; q++) {
                float2 f = __half22float2(hp[q]);
                hp[q] = __floats2half2_rn(f.x * qscale, f.y * qscale);
            }
            *(uint4*)(qd + c8) = u;
        }
    }
    __syncthreads();

    const int aRow = lane & 15, aKoff = (lane & 16) ? 8 : 0;
    uint32_t qf[2][4][4];
    #pragma unroll
    for (int mt = 0; mt < 2; mt++)
        #pragma unroll
        for (int ks = 0; ks < 4; ks++)
            ldsm4(qf[mt][ks], cvs(Qstage + (w * 32 + mt * 16 + aRow) * LDFH
                                     + ks * 16 + aKoff));
    __syncthreads();

    const int nIter = qt + 1;                // 256-key tiles
    const __half* kvb = qkv + (size_t)(b * Tt) * C3 + Cc + h * HSs;

    #define ISSUEF(jb_, s_) do { \
        const __half* kb_ = kvb + (size_t)(jb_) * 256 * C3; \
        uint32_t kd_ = cvs(smf + (s_) * 2 * KBUF); \
        uint32_t vd_ = kd_ + KBUF * 2; \
        _Pragma("unroll") \
        for (int it = 0; it < 8; it++) { \
            int idx = tid + it * 256; \
            int r = idx >> 3, c8 = (idx & 7) << 3; \
            size_t go = (size_t)r * C3 + c8; \
            uint32_t so = (uint32_t)(r * LDFH + c8) * 2u; \
            cp16(kd_ + so, kb_ + go); \
            cp16(vd_ + so, kb_ + Cc + go); \
        } \
        cp_commit(); \
    } while (0)

    ISSUEF(0, 0);

    float accO[2][8][4];
    float lAcc[2][4];
    #pragma unroll
    for (int mt = 0; mt < 2; mt++) {
        #pragma unroll
        for (int j = 0; j < 8; j++)
            #pragma unroll
            for (int q = 0; q < 4; q++) accO[mt][j][q] = 0.f;
        #pragma unroll
        for (int q = 0; q < 4; q++) lAcc[mt][q] = 0.f;
    }
    float mrun[2][2] = {{NEG, NEG}, {NEG, NEG}};
    const uint32_t ONES2 = 0x3C003C00u;
    const uint32_t onesB[2] = {ONES2, ONES2};

    const int kRow = (lane & 7) + ((lane & 8) ? 8 : 0);
    const int kOff = (lane & 16) ? 8 : 0;

    for (int jb = 0; jb < nIter; jb++) {
        const int cur = jb & 1;
        __half* Kt = smf + cur * 2 * KBUF;
        __half* Vt = Kt + KBUF;

        __syncthreads();
        int nxt = jb + 1 < nIter ? jb + 1 : jb;
        ISSUEF(nxt, (jb + 1) & 1);
        cp_wait1();
        __syncthreads();

        #pragma unroll
        for (int sub = 0; sub < 4; sub++) {
            const int kb64 = jb * 4 + sub;
            __half* Ks = Kt + sub * 64 * LDFH;
            __half* Vs = Vt + sub * 64 * LDFH;

            // ---- S = Q x K^T ----
            float sAcc[2][8][4];
            #pragma unroll
            for (int mt = 0; mt < 2; mt++)
                #pragma unroll
                for (int j = 0; j < 8; j++)
                    #pragma unroll
                    for (int q = 0; q < 4; q++) sAcc[mt][j][q] = 0.f;

            #pragma unroll
            for (int ks = 0; ks < 4; ks++) {
                uint32_t kf[8][2];
                #pragma unroll
                for (int j2 = 0; j2 < 4; j2++) {
                    uint32_t t[4];
                    ldsm4(t, cvs(Ks + (j2 * 16 + kRow) * LDFH + ks * 16 + kOff));
                    kf[2 * j2][0] = t[0]; kf[2 * j2][1] = t[2];
                    kf[2 * j2 + 1][0] = t[1]; kf[2 * j2 + 1][1] = t[3];
                }
                #pragma unroll
                for (int nj = 0; nj < 8; nj++) {
                    mma_f16(sAcc[0][nj], qf[0][ks], kf[nj]);
                    mma_f16(sAcc[1][nj], qf[1][ks], kf[nj]);
                }
            }

            // ---- mask + online softmax ----
            uint32_t paf[2][4][4];
            #pragma unroll
            for (int mt = 0; mt < 2; mt++) {
                const int rowA = q0 + w * 32 + mt * 16 + lr;
                const int rowB = rowA + 8;
                if (kb64 * 64 + 63 > q0 + w * 32 + mt * 16) {
                    #pragma unroll
                    for (int nj = 0; nj < 8; nj++) {
                        int col = kb64 * 64 + nj * 8 + 2 * lc;
                        if (col > rowA)     sAcc[mt][nj][0] = NEG;
                        if (col + 1 > rowA) sAcc[mt][nj][1] = NEG;
                        if (col > rowB)     sAcc[mt][nj][2] = NEG;
                        if (col + 1 > rowB) sAcc[mt][nj][3] = NEG;
                    }
                }

                float mxA = NEG, mxB = NEG;
                #pragma unroll
                for (int nj = 0; nj < 8; nj++) {
                    mxA = fmaxf(mxA, fmaxf(sAcc[mt][nj][0], sAcc[mt][nj][1]));
                    mxB = fmaxf(mxB, fmaxf(sAcc[mt][nj][2], sAcc[mt][nj][3]));
                }
                mxA = fmaxf(mxA, __shfl_xor_sync(0xffffffffu, mxA, 1));
                mxA = fmaxf(mxA, __shfl_xor_sync(0xffffffffu, mxA, 2));
                mxB = fmaxf(mxB, __shfl_xor_sync(0xffffffffu, mxB, 1));
                mxB = fmaxf(mxB, __shfl_xor_sync(0xffffffffu, mxB, 2));

                float mn0 = fmaxf(mrun[mt][0], mxA), mn1 = fmaxf(mrun[mt][1], mxB);
                float al0 = ex2(mrun[mt][0] - mn0), al1 = ex2(mrun[mt][1] - mn1);
                mrun[mt][0] = mn0; mrun[mt][1] = mn1;

                #pragma unroll
                for (int ks = 0; ks < 4; ks++) {
                    paf[mt][ks][0] = ex2h2(pk(sAcc[mt][2 * ks][0] - mn0,
                                              sAcc[mt][2 * ks][1] - mn0));
                    paf[mt][ks][1] = ex2h2(pk(sAcc[mt][2 * ks][2] - mn1,
                                              sAcc[mt][2 * ks][3] - mn1));
                    paf[mt][ks][2] = ex2h2(pk(sAcc[mt][2 * ks + 1][0] - mn0,
                                              sAcc[mt][2 * ks + 1][1] - mn0));
                    paf[mt][ks][3] = ex2h2(pk(sAcc[mt][2 * ks + 1][2] - mn1,
                                              sAcc[mt][2 * ks + 1][3] - mn1));
                }

                #pragma unroll
                for (int nj = 0; nj < 8; nj++) {
                    accO[mt][nj][0] *= al0; accO[mt][nj][1] *= al0;
                    accO[mt][nj][2] *= al1; accO[mt][nj][3] *= al1;
                }
                lAcc[mt][0] *= al0; lAcc[mt][1] *= al0;
                lAcc[mt][2] *= al1; lAcc[mt][3] *= al1;

                #pragma unroll
                for (int ks = 0; ks < 4; ks++)
                    mma_f16(lAcc[mt], paf[mt][ks], onesB);
            }

            // ---- O += P x V ----
            #pragma unroll
            for (int ks = 0; ks < 4; ks++) {
                uint32_t vf[8][2];
                #pragma unroll
                for (int j2 = 0; j2 < 4; j2++) {
                    uint32_t t[4];
                    ldsm4t(t, cvs(Vs + (ks * 16 + kRow) * LDFH + j2 * 16 + kOff));
                    vf[2 * j2][0] = t[0]; vf[2 * j2][1] = t[1];
                    vf[2 * j2 + 1][0] = t[2]; vf[2 * j2 + 1][1] = t[3];
                }
                #pragma unroll
                for (int nj = 0; nj < 8; nj++) {
                    mma_f16(accO[0][nj], paf[0][ks], vf[nj]);
                    mma_f16(accO[1][nj], paf[1][ks], vf[nj]);
                }
            }
        }
    }

    cp_wait0();

    __half* obase = out + qrow0 * Cc + h * HSs;
    #pragma unroll
    for (int mt = 0; mt < 2; mt++) {
        int r0 = w * 32 + mt * 16 + lr;
        float rl0 = 1.f / lAcc[mt][0], rl1 = 1.f / lAcc[mt][2];
        #pragma unroll
        for (int nj = 0; nj < 8; nj++) {
            int col = nj * 8 + 2 * lc;
            *(__half2*)(obase + (size_t)r0 * Cc + col) =
                __floats2half2_rn(accO[mt][nj][0] * rl0, accO[mt][nj][1] * rl0);
            *(__half2*)(obase + (size_t)(r0 + 8) * Cc + col) =
                __floats2half2_rn(accO[mt][nj][2] * rl1, accO[mt][nj][3] * rl1);
        }
    }
    #undef ISSUEF
}

// ---------------------------------------------------------------------------
extern "C" void kernel_launch(void* const* d_in, const int* in_sizes, int n_in,
                              void* d_out, int out_size)
{
    const float* x      = (const float*)d_in[0];
    const float* w_attn = (const float*)d_in[1];
    const float* w_proj = (const float*)d_in[2];
    float* out = (float*)d_out;

    __half *qkv, *att, *xh, *wa, *wp;
    cudaGetSymbolAddress((void**)&qkv, g_qkv);
    cudaGetSymbolAddress((void**)&att, g_att);
    cudaGetSymbolAddress((void**)&xh, g_xh);
    cudaGetSymbolAddress((void**)&wa, g_wa);
    cudaGetSymbolAddress((void**)&wp, g_wp);

    const int GEMM_SMEM1 = (2 * 128 * LDAH + 2 * 64 * (256 + 8)) * (int)sizeof(__half); // 104448
    const int GEMM_SMEM2 = (2 * 128 * LDAH + 2 * 64 * (128 + 8)) * (int)sizeof(__half); // 71680
    const int FLASH_SMEM = 4 * KBUF * (int)sizeof(__half);                              // 147456
    cudaFuncSetAttribute(gemm_h16<256, __half>,
                         cudaFuncAttributeMaxDynamicSharedMemorySize, GEMM_SMEM1);
    cudaFuncSetAttribute(gemm_h16<128, float>,
                         cudaFuncAttributeMaxDynamicSharedMemorySize, GEMM_SMEM2);
    cudaFuncSetAttribute(flash_f16,
                         cudaFuncAttributeMaxDynamicSharedMemorySize, FLASH_SMEM);

    // 0) fp32 -> fp16 conversions (single launch)
    {
        int n0 = BT * Cc / 4, n1 = Cc * C3 / 4, n2 = Cc * Cc / 4;
        int nt = n0 + n1 + n2;
        f2h3<<<(nt + 255) / 256, 256>>>(x, xh, n0, w_attn, wa, n1, w_proj, wp, n2);
    }
    // 1) QKV projection (128x256 tiles, kc=64)
    gemm_h16<256, __half><<<dim3(C3 / 256, BT / 128), 256, GEMM_SMEM1>>>(
        xh, wa, qkv, BT, C3, Cc);
    // 2) Causal flash attention (256-key double-buffered stages, LPT order)
    flash_f16<<<(Tt / 256) * NHh * Bb, 256, FLASH_SMEM>>>(qkv, att);
    // 3) Output projection (128x128 tiles, kc=64, 2 CTAs/SM)
    gemm_h16<128, float><<<dim3(Cc / 128, BT / 128), 256, GEMM_SMEM2>>>(
        att, wp, out, BT, Cc, Cc);
}

// round 17
// speedup vs baseline: 1.6621x; 1.0860x over previous
#include <cuda_runtime.h>
#include <cuda_fp16.h>
#include <math.h>
#include <stdint.h>

#define Bb 2
#define Tt 4096
#define Cc 768
#define NHh 12
#define HSs 64
#define BT (Bb*Tt)
#define C3 (3*Cc)

__device__ __half g_qkv[(size_t)BT * C3];   // [B*T, 3C] fp16
__device__ __half g_att[(size_t)BT * Cc];   // [B*T, C]  fp16
__device__ __half g_xh [(size_t)BT * Cc];   // x in fp16
__device__ __half g_wa [(size_t)Cc * C3];   // w_attn fp16
__device__ __half g_wp [(size_t)Cc * Cc];   // w_proj fp16

__device__ __forceinline__ uint32_t h2u(__half2 h) {
    return *reinterpret_cast<uint32_t*>(&h);
}
__device__ __forceinline__ uint32_t pk(float a, float b) {
    __half2 h = __floats2half2_rn(a, b);
    return h2u(h);
}
__device__ __forceinline__ float ex2(float x) {
    float r;
    asm("ex2.approx.ftz.f32 %0, %1;" : "=f"(r) : "f"(x));
    return r;
}
__device__ __forceinline__ uint32_t ex2h2(uint32_t x) {
    uint32_t r;
    asm("ex2.approx.f16x2 %0, %1;" : "=r"(r) : "r"(x));
    return r;
}
__device__ __forceinline__ void cp16(uint32_t dst, const void* src) {
    asm volatile("cp.async.cg.shared.global [%0], [%1], 16;" :: "r"(dst), "l"(src));
}
__device__ __forceinline__ void cp_commit() { asm volatile("cp.async.commit_group;"); }
__device__ __forceinline__ void cp_wait1()  { asm volatile("cp.async.wait_group 1;"); }
__device__ __forceinline__ void cp_wait0()  { asm volatile("cp.async.wait_group 0;"); }

__device__ __forceinline__ void mma_f16(float c[4], const uint32_t a[4], const uint32_t b[2]) {
    asm volatile(
        "mma.sync.aligned.m16n8k16.row.col.f32.f16.f16.f32 "
        "{%0,%1,%2,%3},{%4,%5,%6,%7},{%8,%9},{%0,%1,%2,%3};"
        : "+f"(c[0]), "+f"(c[1]), "+f"(c[2]), "+f"(c[3])
        : "r"(a[0]), "r"(a[1]), "r"(a[2]), "r"(a[3]), "r"(b[0]), "r"(b[1]));
}
__device__ __forceinline__ void ldsm4(uint32_t r[4], uint32_t saddr) {
    asm volatile("ldmatrix.sync.aligned.m8n8.x4.shared.b16 {%0,%1,%2,%3}, [%4];"
                 : "=r"(r[0]), "=r"(r[1]), "=r"(r[2]), "=r"(r[3]) : "r"(saddr));
}
__device__ __forceinline__ void ldsm4t(uint32_t r[4], uint32_t saddr) {
    asm volatile("ldmatrix.sync.aligned.m8n8.x4.trans.shared.b16 {%0,%1,%2,%3}, [%4];"
                 : "=r"(r[0]), "=r"(r[1]), "=r"(r[2]), "=r"(r[3]) : "r"(saddr));
}
__device__ __forceinline__ uint32_t cvs(const void* p) {
    return (uint32_t)__cvta_generic_to_shared(p);
}

// ---------------------------------------------------------------------------
// fp32 -> fp16 bulk convert, all three tensors in one launch
// ---------------------------------------------------------------------------
__global__ void f2h3(const float* __restrict__ s0, __half* __restrict__ d0, int n0,
                     const float* __restrict__ s1, __half* __restrict__ d1, int n1,
                     const float* __restrict__ s2, __half* __restrict__ d2, int n2)
{
    int i = blockIdx.x * blockDim.x + threadIdx.x;
    const float* s; __half* d; int j;
    if (i < n0)           { s = s0; d = d0; j = i; }
    else if (i < n0 + n1) { s = s1; d = d1; j = i - n0; }
    else if (i < n0 + n1 + n2) { s = s2; d = d2; j = i - n0 - n1; }
    else return;
    float4 v = *(const float4*)(s + (size_t)j * 4);
    uint2 u;
    u.x = pk(v.x, v.y);
    u.y = pk(v.z, v.w);
    *(uint2*)(d + (size_t)j * 4) = u;
}

// ---------------------------------------------------------------------------
// All-half GEMM (R16 winner, verbatim): CTA 128xBN, 8 warps (2x4),
// warp 64x(BN/4). kc=64, double-buffered cp.async, 2 syncs per chunk.
// ---------------------------------------------------------------------------
#define LDAH 72   // 64+8: rows 144B apart, ≡16 mod 128 -> ldsm conflict-free

template <int BN, typename TC>
__global__ __launch_bounds__(256)
void gemm_h16(const __half* __restrict__ A, const __half* __restrict__ B,
              TC* __restrict__ C, int M, int N, int K)
{
    constexpr int LDBH = BN + 8;
    constexpr int NTIL = BN / 32;
    constexpr int BIT  = BN / 32;
    constexpr int GA0 = 0, GA1 = 128 * LDAH;
    constexpr int GB0 = 2 * 128 * LDAH, GB1 = GB0 + 64 * LDBH;

    extern __shared__ __half smh[];

    const int tid = threadIdx.x;
    const int lane = tid & 31, wid = tid >> 5;
    const int warpM = wid >> 2, warpN = wid & 3;
    const int lr = lane >> 2, lc = lane & 3;
    const int brow = blockIdx.y << 7;
    const int bcol = blockIdx.x * BN;

    const __half* Ab = A + (size_t)brow * K;
    const __half* Bbp = B + bcol;

    float acc[4][NTIL][4];
    #pragma unroll
    for (int i = 0; i < 4; i++)
        #pragma unroll
        for (int j = 0; j < NTIL; j++)
            #pragma unroll
            for (int q = 0; q < 4; q++) acc[i][j][q] = 0.f;

    #define ISSUE(kt, s) do { \
        uint32_t as_ = cvs(smh + ((s) ? GA1 : GA0)); \
        uint32_t bs_ = cvs(smh + ((s) ? GB1 : GB0)); \
        _Pragma("unroll") \
        for (int it = 0; it < 4; it++) { \
            int idx = tid + it * 256; \
            int r = idx >> 3, c8 = (idx & 7) << 3; \
            cp16(as_ + (uint32_t)(r * LDAH + c8) * 2u, \
                 Ab + (size_t)r * K + (kt) * 64 + c8); \
        } \
        _Pragma("unroll") \
        for (int it = 0; it < BIT; it++) { \
            int idx = tid + it * 256; \
            int r = idx / (BN / 8), c8 = (idx % (BN / 8)) << 3; \
            cp16(bs_ + (uint32_t)(r * LDBH + c8) * 2u, \
                 Bbp + (size_t)((kt) * 64 + r) * N + c8); \
        } \
        cp_commit(); \
    } while (0)

    const int NT = K >> 6;
    ISSUE(0, 0);

    const int aRow = lane & 15, aKoff = (lane & 16) ? 8 : 0;
    const int bRow = (lane & 7) + ((lane & 8) ? 8 : 0);
    const int bNoff = (lane & 16) ? 8 : 0;

    for (int kt = 0; kt < NT; kt++) {
        const int cur = kt & 1;
        if (kt + 1 < NT) { ISSUE(kt + 1, (kt + 1) & 1); cp_wait1(); }
        else cp_wait0();
        __syncthreads();

        const __half* Ac = smh + (cur ? GA1 : GA0);
        const __half* Bc = smh + (cur ? GB1 : GB0);
        #pragma unroll
        for (int ks = 0; ks < 4; ks++) {
            uint32_t af[4][4];
            #pragma unroll
            for (int mt = 0; mt < 4; mt++)
                ldsm4(af[mt], cvs(Ac + (warpM * 64 + mt * 16 + aRow) * LDAH
                                     + ks * 16 + aKoff));
            uint32_t bf[NTIL][2];
            #pragma unroll
            for (int j2 = 0; j2 < NTIL / 2; j2++) {
                uint32_t t[4];
                ldsm4t(t, cvs(Bc + (ks * 16 + bRow) * LDBH
                                 + warpN * (BN / 4) + j2 * 16 + bNoff));
                bf[2 * j2][0] = t[0]; bf[2 * j2][1] = t[1];
                bf[2 * j2 + 1][0] = t[2]; bf[2 * j2 + 1][1] = t[3];
            }
            #pragma unroll
            for (int mt = 0; mt < 4; mt++)
                #pragma unroll
                for (int nt = 0; nt < NTIL; nt++)
                    mma_f16(acc[mt][nt], af[mt], bf[nt]);
        }
        __syncthreads();
    }

    #pragma unroll
    for (int mt = 0; mt < 4; mt++)
        #pragma unroll
        for (int nt = 0; nt < NTIL; nt++) {
            int row = brow + warpM * 64 + mt * 16 + lr;
            int col = bcol + warpN * (BN / 4) + nt * 8 + 2 * lc;
            if constexpr (sizeof(TC) == 2) {
                *(__half2*)&C[(size_t)row * N + col] =
                    __floats2half2_rn(acc[mt][nt][0], acc[mt][nt][1]);
                *(__half2*)&C[(size_t)(row + 8) * N + col] =
                    __floats2half2_rn(acc[mt][nt][2], acc[mt][nt][3]);
            } else {
                *(float2*)&C[(size_t)row * N + col] =
                    make_float2(acc[mt][nt][0], acc[mt][nt][1]);
                *(float2*)&C[(size_t)(row + 8) * N + col] =
                    make_float2(acc[mt][nt][2], acc[mt][nt][3]);
            }
        }
    #undef ISSUE
}

// ---------------------------------------------------------------------------
// Causal flash attention, 2 CTA/SM variant: 128 q/CTA, 8 warps, warp owns
// 16 q-rows x 64 keys. fp16 mma, register softmax (base-2), f16x2 exp,
// l via ones-mma. 128-key double-buffered stages, LPT heavy-first 1-D grid.
// ---------------------------------------------------------------------------
#define LDFH 72
#define KBUF (128 * LDFH)       // one 128x64 tile (halfs)

__global__ __launch_bounds__(256, 2)
void flash_f16(const __half* __restrict__ qkv, __half* __restrict__ out)
{
    extern __shared__ __half smf[];
    __half* Qstage = smf;       // 128*LDFH halfs (overlaps stage buffers)

    const int NQT = Tt / 128;                 // 32
    const int qt = NQT - 1 - ((int)blockIdx.x / (NHh * Bb));
    const int hb = (int)blockIdx.x % (NHh * Bb);
    const int h = hb % NHh, b = hb / NHh;

    const int tid = threadIdx.x;
    const int lane = tid & 31, w = tid >> 5;
    const int lr = lane >> 2, lc = lane & 3;
    const float NEG = -1e30f;
    const float qscale = 0.125f * 1.44269504089f;

    const int q0 = qt * 128;
    const size_t qrow0 = (size_t)(b * Tt + q0);
    const __half* qbase = qkv + qrow0 * C3 + h * HSs;

    // stage Q (scaled): 128 rows x 64 cols; each thread does half a row
    {
        int r = tid >> 1, c0 = (tid & 1) << 5;   // 32-col half
        const __half* qr = qbase + (size_t)r * C3 + c0;
        __half* qd = Qstage + r * LDFH + c0;
        #pragma unroll
        for (int c8 = 0; c8 < 32; c8 += 8) {
            uint4 u = *(const uint4*)(qr + c8);
            __half2* hp = (__half2*)&u;
            #pragma unroll
            for (int q = 0; q < 4; q++) {
                float2 f = __half22float2(hp[q]);
                hp[q] = __floats2half2_rn(f.x * qscale, f.y * qscale);
            }
            *(uint4*)(qd + c8) = u;
        }
    }
    __syncthreads();

    const int aRow = lane & 15, aKoff = (lane & 16) ? 8 : 0;
    uint32_t qf[4][4];
    #pragma unroll
    for (int ks = 0; ks < 4; ks++)
        ldsm4(qf[ks], cvs(Qstage + (w * 16 + aRow) * LDFH + ks * 16 + aKoff));
    __syncthreads();

    const int nIter = qt + 1;                // 128-key tiles
    const __half* kvb = qkv + (size_t)(b * Tt) * C3 + Cc + h * HSs;

    #define ISSUEF(jb_, s_) do { \
        const __half* kb_ = kvb + (size_t)(jb_) * 128 * C3; \
        uint32_t kd_ = cvs(smf + (s_) * 2 * KBUF); \
        uint32_t vd_ = kd_ + KBUF * 2; \
        _Pragma("unroll") \
        for (int it = 0; it < 4; it++) { \
            int idx = tid + it * 256; \
            int r = idx >> 3, c8 = (idx & 7) << 3; \
            size_t go = (size_t)r * C3 + c8; \
            uint32_t so = (uint32_t)(r * LDFH + c8) * 2u; \
            cp16(kd_ + so, kb_ + go); \
            cp16(vd_ + so, kb_ + Cc + go); \
        } \
        cp_commit(); \
    } while (0)

    ISSUEF(0, 0);

    float accO[8][4];
    float lAcc[4];
    #pragma unroll
    for (int j = 0; j < 8; j++)
        #pragma unroll
        for (int q = 0; q < 4; q++) accO[j][q] = 0.f;
    #pragma unroll
    for (int q = 0; q < 4; q++) lAcc[q] = 0.f;
    float m0 = NEG, m1 = NEG;
    const uint32_t ONES2 = 0x3C003C00u;
    const uint32_t onesB[2] = {ONES2, ONES2};

    const int kRow = (lane & 7) + ((lane & 8) ? 8 : 0);
    const int kOff = (lane & 16) ? 8 : 0;
    const int rowA = q0 + w * 16 + lr;
    const int rowB = rowA + 8;

    for (int jb = 0; jb < nIter; jb++) {
        const int cur = jb & 1;
        __half* Kt = smf + cur * 2 * KBUF;
        __half* Vt = Kt + KBUF;

        __syncthreads();
        int nxt = jb + 1 < nIter ? jb + 1 : jb;
        ISSUEF(nxt, (jb + 1) & 1);
        cp_wait1();
        __syncthreads();

        #pragma unroll
        for (int sub = 0; sub < 2; sub++) {
            const int kb64 = jb * 2 + sub;
            __half* Ks = Kt + sub * 64 * LDFH;
            __half* Vs = Vt + sub * 64 * LDFH;

            // ---- S = Q x K^T ----
            float sAcc[8][4];
            #pragma unroll
            for (int j = 0; j < 8; j++)
                #pragma unroll
                for (int q = 0; q < 4; q++) sAcc[j][q] = 0.f;

            #pragma unroll
            for (int ks = 0; ks < 4; ks++) {
                uint32_t kf[8][2];
                #pragma unroll
                for (int j2 = 0; j2 < 4; j2++) {
                    uint32_t t[4];
                    ldsm4(t, cvs(Ks + (j2 * 16 + kRow) * LDFH + ks * 16 + kOff));
                    kf[2 * j2][0] = t[0]; kf[2 * j2][1] = t[2];
                    kf[2 * j2 + 1][0] = t[1]; kf[2 * j2 + 1][1] = t[3];
                }
                #pragma unroll
                for (int nj = 0; nj < 8; nj++)
                    mma_f16(sAcc[nj], qf[ks], kf[nj]);
            }

            // ---- causal mask ----
            if (kb64 * 64 + 63 > q0 + w * 16) {
                #pragma unroll
                for (int nj = 0; nj < 8; nj++) {
                    int col = kb64 * 64 + nj * 8 + 2 * lc;
                    if (col > rowA)     sAcc[nj][0] = NEG;
                    if (col + 1 > rowA) sAcc[nj][1] = NEG;
                    if (col > rowB)     sAcc[nj][2] = NEG;
                    if (col + 1 > rowB) sAcc[nj][3] = NEG;
                }
            }

            // ---- online softmax (base 2) ----
            float mxA = NEG, mxB = NEG;
            #pragma unroll
            for (int nj = 0; nj < 8; nj++) {
                mxA = fmaxf(mxA, fmaxf(sAcc[nj][0], sAcc[nj][1]));
                mxB = fmaxf(mxB, fmaxf(sAcc[nj][2], sAcc[nj][3]));
            }
            mxA = fmaxf(mxA, __shfl_xor_sync(0xffffffffu, mxA, 1));
            mxA = fmaxf(mxA, __shfl_xor_sync(0xffffffffu, mxA, 2));
            mxB = fmaxf(mxB, __shfl_xor_sync(0xffffffffu, mxB, 1));
            mxB = fmaxf(mxB, __shfl_xor_sync(0xffffffffu, mxB, 2));

            float mn0 = fmaxf(m0, mxA), mn1 = fmaxf(m1, mxB);
            float al0 = ex2(m0 - mn0), al1 = ex2(m1 - mn1);
            m0 = mn0; m1 = mn1;

            uint32_t paf[4][4];
            #pragma unroll
            for (int ks = 0; ks < 4; ks++) {
                paf[ks][0] = ex2h2(pk(sAcc[2 * ks][0] - mn0, sAcc[2 * ks][1] - mn0));
                paf[ks][1] = ex2h2(pk(sAcc[2 * ks][2] - mn1, sAcc[2 * ks][3] - mn1));
                paf[ks][2] = ex2h2(pk(sAcc[2 * ks + 1][0] - mn0, sAcc[2 * ks + 1][1] - mn0));
                paf[ks][3] = ex2h2(pk(sAcc[2 * ks + 1][2] - mn1, sAcc[2 * ks + 1][3] - mn1));
            }

            #pragma unroll
            for (int nj = 0; nj < 8; nj++) {
                accO[nj][0] *= al0; accO[nj][1] *= al0;
                accO[nj][2] *= al1; accO[nj][3] *= al1;
            }
            lAcc[0] *= al0; lAcc[1] *= al0;
            lAcc[2] *= al1; lAcc[3] *= al1;

            #pragma unroll
            for (int ks = 0; ks < 4; ks++)
                mma_f16(lAcc, paf[ks], onesB);

            // ---- O += P x V ----
            #pragma unroll
            for (int ks = 0; ks < 4; ks++) {
                uint32_t vf[8][2];
                #pragma unroll
                for (int j2 = 0; j2 < 4; j2++) {
                    uint32_t t[4];
                    ldsm4t(t, cvs(Vs + (ks * 16 + kRow) * LDFH + j2 * 16 + kOff));
                    vf[2 * j2][0] = t[0]; vf[2 * j2][1] = t[1];
                    vf[2 * j2 + 1][0] = t[2]; vf[2 * j2 + 1][1] = t[3];
                }
                #pragma unroll
                for (int nj = 0; nj < 8; nj++)
                    mma_f16(accO[nj], paf[ks], vf[nj]);
            }
        }
    }

    cp_wait0();

    __half* obase = out + qrow0 * Cc + h * HSs;
    {
        int r0 = w * 16 + lr;
        float rl0 = 1.f / lAcc[0], rl1 = 1.f / lAcc[2];
        #pragma unroll
        for (int nj = 0; nj < 8; nj++) {
            int col = nj * 8 + 2 * lc;
            *(__half2*)(obase + (size_t)r0 * Cc + col) =
                __floats2half2_rn(accO[nj][0] * rl0, accO[nj][1] * rl0);
            *(__half2*)(obase + (size_t)(r0 + 8) * Cc + col) =
                __floats2half2_rn(accO[nj][2] * rl1, accO[nj][3] * rl1);
        }
    }
    #undef ISSUEF
}

// ---------------------------------------------------------------------------
extern "C" void kernel_launch(void* const* d_in, const int* in_sizes, int n_in,
                              void* d_out, int out_size)
{
    const float* x      = (const float*)d_in[0];
    const float* w_attn = (const float*)d_in[1];
    const float* w_proj = (const float*)d_in[2];
    float* out = (float*)d_out;

    __half *qkv, *att, *xh, *wa, *wp;
    cudaGetSymbolAddress((void**)&qkv, g_qkv);
    cudaGetSymbolAddress((void**)&att, g_att);
    cudaGetSymbolAddress((void**)&xh, g_xh);
    cudaGetSymbolAddress((void**)&wa, g_wa);
    cudaGetSymbolAddress((void**)&wp, g_wp);

    const int GEMM_SMEM1 = (2 * 128 * LDAH + 2 * 64 * (256 + 8)) * (int)sizeof(__half); // 104448
    const int GEMM_SMEM2 = (2 * 128 * LDAH + 2 * 64 * (128 + 8)) * (int)sizeof(__half); // 71680
    const int FLASH_SMEM = 4 * KBUF * (int)sizeof(__half);                              // 73728
    cudaFuncSetAttribute(gemm_h16<256, __half>,
                         cudaFuncAttributeMaxDynamicSharedMemorySize, GEMM_SMEM1);
    cudaFuncSetAttribute(gemm_h16<128, float>,
                         cudaFuncAttributeMaxDynamicSharedMemorySize, GEMM_SMEM2);
    cudaFuncSetAttribute(flash_f16,
                         cudaFuncAttributeMaxDynamicSharedMemorySize, FLASH_SMEM);

    // 0) fp32 -> fp16 conversions (single launch)
    {
        int n0 = BT * Cc / 4, n1 = Cc * C3 / 4, n2 = Cc * Cc / 4;
        int nt = n0 + n1 + n2;
        f2h3<<<(nt + 255) / 256, 256>>>(x, xh, n0, w_attn, wa, n1, w_proj, wp, n2);
    }
    // 1) QKV projection (128x256 tiles, kc=64)
    gemm_h16<256, __half><<<dim3(C3 / 256, BT / 128), 256, GEMM_SMEM1>>>(
        xh, wa, qkv, BT, C3, Cc);
    // 2) Causal flash attention (128 q/CTA, 2 CTA/SM, LPT order)
    flash_f16<<<(Tt / 128) * NHh * Bb, 256, FLASH_SMEM>>>(qkv, att);
    // 3) Output projection (128x128 tiles, kc=64)
    gemm_h16<128, float><<<dim3(Cc / 128, BT / 128), 256, GEMM_SMEM2>>>(
        att, wp, out, BT, Cc, Cc);
}